// round 1
// baseline (speedup 1.0000x reference)
#include <cuda_runtime.h>
#include <cuda_bf16.h>
#include <math.h>

// ---------------- problem constants ----------------
#define Dm     512      // d_model
#define DIN    1024     // expand * D
#define Hh     16       // heads
#define Pp     64       // headdim
#define Rr     4        // mimo rank
#define Ns     32       // d_state
#define HRDS   2048     // H*R*DS
#define DFF    1368
#define BB     4
#define SS     512
#define TT     (BB*SS)  // 2048 tokens

// ---------------- static scratch (no allocations allowed) ----------------
__device__ float g_xn  [TT*Dm];
__device__ float g_z   [TT*DIN];
__device__ float g_u   [TT*DIN];
__device__ float g_Bm  [TT*HRDS];
__device__ float g_Cm  [TT*HRDS];
__device__ float g_dt  [TT*Hh];
__device__ float g_a   [TT*Hh];
__device__ float g_gy  [TT*DIN];   // gated y (scan output * silu(z))
__device__ float g_yo  [TT*Dm];    // y @ Wout
__device__ float g_x1  [TT*Dm];    // residual 1
__device__ float g_xn2 [TT*Dm];
__device__ float g_g1  [TT*DFF];
__device__ float g_g3  [TT*DFF];
__device__ float g_f   [TT*Dm];

// ---------------- rmsnorm (optionally masked output) ----------------
__global__ void rmsnorm_kernel(const float* __restrict__ x,
                               const float* __restrict__ w,
                               const float* __restrict__ mask,
                               float* __restrict__ out, int useMask) {
    int t = blockIdx.x;
    const float* xr = x + (size_t)t * Dm;
    float s = 0.f;
    for (int i = threadIdx.x; i < Dm; i += blockDim.x) { float v = xr[i]; s += v * v; }
    __shared__ float red[32];
    #pragma unroll
    for (int o = 16; o; o >>= 1) s += __shfl_down_sync(0xFFFFFFFFu, s, o);
    if ((threadIdx.x & 31) == 0) red[threadIdx.x >> 5] = s;
    __syncthreads();
    if (threadIdx.x < 32) {
        float v = (threadIdx.x < (blockDim.x >> 5)) ? red[threadIdx.x] : 0.f;
        #pragma unroll
        for (int o = 16; o; o >>= 1) v += __shfl_down_sync(0xFFFFFFFFu, v, o);
        if (threadIdx.x == 0) red[0] = v;
    }
    __syncthreads();
    float inv = rsqrtf(red[0] / (float)Dm + 1e-6f);
    float m = useMask ? mask[t] : 1.f;
    float* orow = out + (size_t)t * Dm;
    for (int i = threadIdx.x; i < Dm; i += blockDim.x)
        orow[i] = xr[i] * inv * w[i] * m;
}

// ---------------- fp32 SGEMM: C[M,N] = A[M,K] @ B[K,N], 128x128x8, 8x8/thread ----------------
__global__ __launch_bounds__(256, 2)
void sgemm128(const float* __restrict__ A, const float* __restrict__ B,
              float* __restrict__ C, int M, int N, int K) {
    __shared__ float As[8][132];
    __shared__ float Bs[8][128];
    int bm = blockIdx.y * 128, bn = blockIdx.x * 128;
    int tid = threadIdx.x;
    int tr = tid >> 4, tc = tid & 15;          // 16x16 threads
    float acc[8][8];
    #pragma unroll
    for (int i = 0; i < 8; i++)
        #pragma unroll
        for (int j = 0; j < 8; j++) acc[i][j] = 0.f;

    for (int k0 = 0; k0 < K; k0 += 8) {
        // load A tile 128x8 -> As[k][m]
        #pragma unroll
        for (int l = 0; l < 4; l++) {
            int idx = tid + l * 256;           // 0..1023
            int m = idx >> 3, k = idx & 7;
            int gm = bm + m, gk = k0 + k;
            As[k][m] = (gm < M && gk < K) ? A[(size_t)gm * K + gk] : 0.f;
        }
        // load B tile 8x128 -> Bs[k][n]
        #pragma unroll
        for (int l = 0; l < 4; l++) {
            int idx = tid + l * 256;
            int k = idx >> 7, n = idx & 127;
            int gk = k0 + k, gn = bn + n;
            Bs[k][n] = (gk < K && gn < N) ? B[(size_t)gk * N + gn] : 0.f;
        }
        __syncthreads();
        #pragma unroll
        for (int k = 0; k < 8; k++) {
            float av[8], bv[8];
            #pragma unroll
            for (int i = 0; i < 8; i++) av[i] = As[k][tr * 8 + i];
            #pragma unroll
            for (int j = 0; j < 8; j++) bv[j] = Bs[k][tc * 8 + j];
            #pragma unroll
            for (int i = 0; i < 8; i++)
                #pragma unroll
                for (int j = 0; j < 8; j++) acc[i][j] += av[i] * bv[j];
        }
        __syncthreads();
    }
    #pragma unroll
    for (int i = 0; i < 8; i++) {
        int gm = bm + tr * 8 + i;
        if (gm >= M) continue;
        #pragma unroll
        for (int j = 0; j < 8; j++) {
            int gn = bn + tc * 8 + j;
            if (gn < N) C[(size_t)gm * N + gn] = acc[i][j];
        }
    }
}

// ---------------- dt / decay: one warp per head ----------------
__global__ void dt_kernel(const float* __restrict__ xn, const float* __restrict__ Wdt,
                          const float* __restrict__ dt_bias, const float* __restrict__ A_log,
                          float* __restrict__ dt, float* __restrict__ a) {
    int t = blockIdx.x;
    int warp = threadIdx.x >> 5, lane = threadIdx.x & 31;   // 16 warps = 16 heads
    const float* xr = xn + (size_t)t * Dm;
    float s = 0.f;
    for (int i = lane; i < Dm; i += 32) s += xr[i] * Wdt[(size_t)i * Hh + warp];
    #pragma unroll
    for (int o = 16; o; o >>= 1) s += __shfl_down_sync(0xFFFFFFFFu, s, o);
    if (lane == 0) {
        s += dt_bias[warp];
        float sp = (s > 20.f) ? s : log1pf(expf(s));   // softplus
        dt[(size_t)t * Hh + warp] = sp;
        a[(size_t)t * Hh + warp] = expf(-expf(A_log[warp]) * sp);
    }
}

// ---------------- sequential SSM scan, one block per (b,h) ----------------
// state h[r,n,p] (4*32*64=8192 floats) lives in registers: thread (g,p) owns r=g, all n.
__global__ __launch_bounds__(256, 1)
void scan_kernel(const float* __restrict__ Bm, const float* __restrict__ Cm,
                 const float* __restrict__ u,  const float* __restrict__ dt,
                 const float* __restrict__ a,  const float* __restrict__ z,
                 const float* __restrict__ Dskip, float* __restrict__ gy) {
    int b = blockIdx.x >> 4, h = blockIdx.x & 15;
    int tid = threadIdx.x;
    int g = tid >> 6, p = tid & 63;       // g = r (rank), p = head-dim position
    __shared__ float Bs[128], Cs[128], uds[64], red[256], sc[1];
    float hst[32];
    #pragma unroll
    for (int i = 0; i < 32; i++) hst[i] = 0.f;
    float dsk = Dskip[h];

    for (int s = 0; s < SS; s++) {
        int base = (b * SS + s) * Hh + h;
        if (tid < 128)      Bs[tid]       = Bm[(size_t)base * 128 + tid];
        else                Cs[tid - 128] = Cm[(size_t)base * 128 + (tid - 128)];
        if (tid < 64)       uds[tid]      = u[(size_t)base * 64 + tid] * dt[base];
        if (tid == 0)       sc[0]         = a[base];
        __syncthreads();
        float av = sc[0];
        float udp = uds[p];
        float acc = 0.f;
        #pragma unroll
        for (int i = 0; i < 32; i++) {
            float hv = av * hst[i] + Bs[g * 32 + i] * udp;
            hst[i] = hv;
            acc += Cs[g * 32 + i] * hv;
        }
        red[tid] = acc;
        __syncthreads();
        if (tid < 64) {
            float y = red[tid] + red[tid + 64] + red[tid + 128] + red[tid + 192];
            float uv = u[(size_t)base * 64 + tid];
            size_t zi = ((size_t)(b * SS + s)) * DIN + h * 64 + tid;
            float zv = z[zi];
            float sz = zv / (1.f + expf(-zv));         // silu
            gy[zi] = (y + uv * dsk) * sz;
        }
    }
}

// ---------------- pointwise ----------------
__global__ void residual_mask_kernel(const float* __restrict__ x, const float* __restrict__ y,
                                     const float* __restrict__ mask, float* __restrict__ out, int n) {
    int i = blockIdx.x * blockDim.x + threadIdx.x;
    if (i < n) out[i] = x[i] + y[i] * mask[i / Dm];
}
__global__ void swiglu_kernel(float* __restrict__ g1, const float* __restrict__ g3, int n) {
    int i = blockIdx.x * blockDim.x + threadIdx.x;
    if (i < n) { float v = g1[i]; g1[i] = (v / (1.f + expf(-v))) * g3[i]; }
}
__global__ void final_kernel(const float* __restrict__ x1, const float* __restrict__ f,
                             const float* __restrict__ mask, float* __restrict__ out, int n) {
    int i = blockIdx.x * blockDim.x + threadIdx.x;
    if (i < n) out[i] = (x1[i] + f[i]) * mask[i / Dm];
}

// ---------------- launch ----------------
static inline dim3 gemm_grid(int M, int N) { return dim3((N + 127) / 128, (M + 127) / 128); }

extern "C" void kernel_launch(void* const* d_in, const int* in_sizes, int n_in,
                              void* d_out, int out_size) {
    const float* x      = (const float*)d_in[0];
    const float* mask   = (const float*)d_in[1];
    const float* n1w    = (const float*)d_in[2];
    const float* n2w    = (const float*)d_in[3];
    const float* Wz     = (const float*)d_in[4];
    const float* Wx     = (const float*)d_in[5];
    const float* Wb     = (const float*)d_in[6];
    const float* Wc     = (const float*)d_in[7];
    const float* Wdt    = (const float*)d_in[8];
    const float* dtb    = (const float*)d_in[9];
    const float* A_log  = (const float*)d_in[10];
    const float* D_skip = (const float*)d_in[11];
    const float* Wout   = (const float*)d_in[12];
    const float* w1     = (const float*)d_in[13];
    const float* w2     = (const float*)d_in[14];
    const float* w3     = (const float*)d_in[15];
    float* out = (float*)d_out;

    float *xn, *z, *u, *bm, *cm, *dt, *a, *gy, *yo, *x1, *xn2, *g1, *g3, *f;
    cudaGetSymbolAddress((void**)&xn,  g_xn);
    cudaGetSymbolAddress((void**)&z,   g_z);
    cudaGetSymbolAddress((void**)&u,   g_u);
    cudaGetSymbolAddress((void**)&bm,  g_Bm);
    cudaGetSymbolAddress((void**)&cm,  g_Cm);
    cudaGetSymbolAddress((void**)&dt,  g_dt);
    cudaGetSymbolAddress((void**)&a,   g_a);
    cudaGetSymbolAddress((void**)&gy,  g_gy);
    cudaGetSymbolAddress((void**)&yo,  g_yo);
    cudaGetSymbolAddress((void**)&x1,  g_x1);
    cudaGetSymbolAddress((void**)&xn2, g_xn2);
    cudaGetSymbolAddress((void**)&g1,  g_g1);
    cudaGetSymbolAddress((void**)&g3,  g_g3);
    cudaGetSymbolAddress((void**)&f,   g_f);

    // 1. xn = rmsnorm(x, n1w) * mask
    rmsnorm_kernel<<<TT, 256>>>(x, n1w, mask, xn, 1);
    // 2. projections
    sgemm128<<<gemm_grid(TT, DIN),  256>>>(xn, Wz, z,  TT, DIN,  Dm);
    sgemm128<<<gemm_grid(TT, DIN),  256>>>(xn, Wx, u,  TT, DIN,  Dm);
    sgemm128<<<gemm_grid(TT, HRDS), 256>>>(xn, Wb, bm, TT, HRDS, Dm);
    sgemm128<<<gemm_grid(TT, HRDS), 256>>>(xn, Wc, cm, TT, HRDS, Dm);
    // 3. dt / decay
    dt_kernel<<<TT, 512>>>(xn, Wdt, dtb, A_log, dt, a);
    // 4. scan + D-skip + silu(z) gate  -> gy
    scan_kernel<<<BB * Hh, 256>>>(bm, cm, u, dt, a, z, D_skip, gy);
    // 5. out-proj + masked residual
    sgemm128<<<gemm_grid(TT, Dm), 256>>>(gy, Wout, yo, TT, Dm, DIN);
    residual_mask_kernel<<<(TT * Dm + 255) / 256, 256>>>(x, yo, mask, x1, TT * Dm);
    // 6. FFN
    rmsnorm_kernel<<<TT, 256>>>(x1, n2w, mask, xn2, 0);
    sgemm128<<<gemm_grid(TT, DFF), 256>>>(xn2, w1, g1, TT, DFF, Dm);
    sgemm128<<<gemm_grid(TT, DFF), 256>>>(xn2, w3, g3, TT, DFF, Dm);
    swiglu_kernel<<<(TT * DFF + 255) / 256, 256>>>(g1, g3, TT * DFF);
    sgemm128<<<gemm_grid(TT, Dm), 256>>>(g1, w2, f, TT, Dm, DFF);
    final_kernel<<<(TT * Dm + 255) / 256, 256>>>(x1, f, mask, out, TT * Dm);
}

// round 2
// speedup vs baseline: 1.8656x; 1.8656x over previous
#include <cuda_runtime.h>
#include <cuda_bf16.h>
#include <math.h>
#include <stdint.h>

// ---------------- problem constants ----------------
#define Dm     512
#define DIN    1024
#define Hh     16
#define Pp     64
#define Rr     4
#define Ns     32
#define HRDS   2048
#define DFF    1368
#define BB     4
#define SS     512
#define TT     (BB*SS)

// ---------------- static scratch ----------------
__device__ float g_xn  [TT*Dm];
__device__ float g_z   [TT*DIN];
__device__ float g_u   [TT*DIN];
__device__ float g_Bm  [TT*HRDS];
__device__ float g_Cm  [TT*HRDS];
__device__ float g_dt  [TT*Hh];
__device__ float g_a   [TT*Hh];
__device__ float g_gy  [TT*DIN];
__device__ float g_x1  [TT*Dm];
__device__ float g_xn2 [TT*Dm];
__device__ float g_g1  [TT*DFF];
__device__ float g_g3  [TT*DFF];

// ---------------- rmsnorm ----------------
__global__ void rmsnorm_kernel(const float* __restrict__ x,
                               const float* __restrict__ w,
                               const float* __restrict__ mask,
                               float* __restrict__ out, int useMask) {
    int t = blockIdx.x;
    const float* xr = x + (size_t)t * Dm;
    float s = 0.f;
    for (int i = threadIdx.x; i < Dm; i += blockDim.x) { float v = xr[i]; s += v * v; }
    __shared__ float red[32];
    #pragma unroll
    for (int o = 16; o; o >>= 1) s += __shfl_down_sync(0xFFFFFFFFu, s, o);
    if ((threadIdx.x & 31) == 0) red[threadIdx.x >> 5] = s;
    __syncthreads();
    if (threadIdx.x < 32) {
        float v = (threadIdx.x < (blockDim.x >> 5)) ? red[threadIdx.x] : 0.f;
        #pragma unroll
        for (int o = 16; o; o >>= 1) v += __shfl_down_sync(0xFFFFFFFFu, v, o);
        if (threadIdx.x == 0) red[0] = v;
    }
    __syncthreads();
    float inv = rsqrtf(red[0] / (float)Dm + 1e-6f);
    float m = useMask ? mask[t] : 1.f;
    float* orow = out + (size_t)t * Dm;
    for (int i = threadIdx.x; i < Dm; i += blockDim.x)
        orow[i] = xr[i] * inv * w[i] * m;
}

// ---------------- tf32 tensor-core GEMM ----------------
__device__ __forceinline__ void mma_tf32(float* c, const uint32_t* a, const uint32_t* b) {
    asm volatile("mma.sync.aligned.m16n8k8.row.col.f32.tf32.tf32.f32 "
        "{%0,%1,%2,%3}, {%4,%5,%6,%7}, {%8,%9}, {%0,%1,%2,%3};"
        : "+f"(c[0]), "+f"(c[1]), "+f"(c[2]), "+f"(c[3])
        : "r"(a[0]), "r"(a[1]), "r"(a[2]), "r"(a[3]), "r"(b[0]), "r"(b[1]));
}
__device__ __forceinline__ uint32_t f2tf32(float v) {
    uint32_t u; asm("cvt.rna.tf32.f32 %0, %1;" : "=r"(u) : "f"(v)); return u;
}

// C[M,N] = A[M,K] @ B[K,N]; block tile 128x128x16, 8 warps (4x2), warp tile 32x64.
// mode 0: C=acc
// mode 1: C=res+acc*mask[row]
// mode 2: C=(res+acc)*mask[row]
// mode 3: C=silu(acc)
// mode 4: C=res*acc
__global__ __launch_bounds__(256)
void mma_gemm(const float* __restrict__ A, const float* __restrict__ B,
              float* __restrict__ C, int M, int N, int K,
              int mode, const float* __restrict__ res, const float* __restrict__ mask) {
    __shared__ uint32_t As[2][128 * 20];
    __shared__ uint32_t Bs[2][16 * 136];
    const int bm = blockIdx.y * 128, bn = blockIdx.x * 128;
    const int tid = threadIdx.x;
    const int lane = tid & 31, w = tid >> 5;
    const int wm = (w >> 1) * 32, wn = (w & 1) * 64;
    const int g = lane >> 2, tg = lane & 3;

    float acc[2][8][4];
    #pragma unroll
    for (int mt = 0; mt < 2; mt++)
        #pragma unroll
        for (int nt = 0; nt < 8; nt++)
            #pragma unroll
            for (int q = 0; q < 4; q++) acc[mt][nt][q] = 0.f;

    const int kIter = (K + 15) / 16;

    // ---- prologue: stage 0 direct to smem ----
    {
        const int k0 = 0;
        #pragma unroll
        for (int i = 0; i < 2; i++) {
            int l = tid + i * 256;
            int m = l >> 2, kq = (l & 3) * 4;
            const float* src = A + (size_t)(bm + m) * K + k0 + kq;
            uint4 pv;
            if (k0 + 16 <= K) {
                float4 v = *(const float4*)src;
                pv.x = f2tf32(v.x); pv.y = f2tf32(v.y); pv.z = f2tf32(v.z); pv.w = f2tf32(v.w);
            } else {
                float t0 = (k0+kq+0 < K) ? src[0] : 0.f;
                float t1 = (k0+kq+1 < K) ? src[1] : 0.f;
                float t2 = (k0+kq+2 < K) ? src[2] : 0.f;
                float t3 = (k0+kq+3 < K) ? src[3] : 0.f;
                pv.x = f2tf32(t0); pv.y = f2tf32(t1); pv.z = f2tf32(t2); pv.w = f2tf32(t3);
            }
            *(uint4*)&As[0][m * 20 + kq] = pv;
        }
        #pragma unroll
        for (int i = 0; i < 2; i++) {
            int l = tid + i * 256;
            int kk = l >> 5, nq = (l & 31) * 4;
            const float* src = B + (size_t)(k0 + kk) * N + bn + nq;
            bool kok = (k0 + kk < K);
            uint4 pv;
            if (kok && (bn + nq + 3) < N) {
                float4 v = *(const float4*)src;
                pv.x = f2tf32(v.x); pv.y = f2tf32(v.y); pv.z = f2tf32(v.z); pv.w = f2tf32(v.w);
            } else {
                float t0 = (kok && bn+nq+0 < N) ? src[0] : 0.f;
                float t1 = (kok && bn+nq+1 < N) ? src[1] : 0.f;
                float t2 = (kok && bn+nq+2 < N) ? src[2] : 0.f;
                float t3 = (kok && bn+nq+3 < N) ? src[3] : 0.f;
                pv.x = f2tf32(t0); pv.y = f2tf32(t1); pv.z = f2tf32(t2); pv.w = f2tf32(t3);
            }
            *(uint4*)&Bs[0][kk * 136 + nq] = pv;
        }
    }
    __syncthreads();

    for (int it = 0; it < kIter; it++) {
        const int cur = it & 1;
        const bool has = (it + 1 < kIter);
        float ar[8], br[8];
        if (has) {
            const int k0 = (it + 1) * 16;
            #pragma unroll
            for (int i = 0; i < 2; i++) {
                int l = tid + i * 256;
                int m = l >> 2, kq = (l & 3) * 4;
                const float* src = A + (size_t)(bm + m) * K + k0 + kq;
                if (k0 + 16 <= K) {
                    float4 v = *(const float4*)src;
                    ar[i*4+0]=v.x; ar[i*4+1]=v.y; ar[i*4+2]=v.z; ar[i*4+3]=v.w;
                } else {
                    ar[i*4+0] = (k0+kq+0 < K) ? src[0] : 0.f;
                    ar[i*4+1] = (k0+kq+1 < K) ? src[1] : 0.f;
                    ar[i*4+2] = (k0+kq+2 < K) ? src[2] : 0.f;
                    ar[i*4+3] = (k0+kq+3 < K) ? src[3] : 0.f;
                }
            }
            #pragma unroll
            for (int i = 0; i < 2; i++) {
                int l = tid + i * 256;
                int kk = l >> 5, nq = (l & 31) * 4;
                const float* src = B + (size_t)(k0 + kk) * N + bn + nq;
                bool kok = (k0 + kk < K);
                if (kok && (bn + nq + 3) < N) {
                    float4 v = *(const float4*)src;
                    br[i*4+0]=v.x; br[i*4+1]=v.y; br[i*4+2]=v.z; br[i*4+3]=v.w;
                } else {
                    br[i*4+0] = (kok && bn+nq+0 < N) ? src[0] : 0.f;
                    br[i*4+1] = (kok && bn+nq+1 < N) ? src[1] : 0.f;
                    br[i*4+2] = (kok && bn+nq+2 < N) ? src[2] : 0.f;
                    br[i*4+3] = (kok && bn+nq+3 < N) ? src[3] : 0.f;
                }
            }
        }

        // ---- compute on smem[cur] ----
        const uint32_t* as = As[cur];
        const uint32_t* bs = Bs[cur];
        #pragma unroll
        for (int kh = 0; kh < 2; kh++) {
            const int kb = kh * 8;
            uint32_t af[2][4];
            #pragma unroll
            for (int mt = 0; mt < 2; mt++) {
                int mr = wm + mt * 16 + g;
                af[mt][0] = as[mr * 20 + kb + tg];
                af[mt][1] = as[(mr + 8) * 20 + kb + tg];
                af[mt][2] = as[mr * 20 + kb + tg + 4];
                af[mt][3] = as[(mr + 8) * 20 + kb + tg + 4];
            }
            #pragma unroll
            for (int nt = 0; nt < 8; nt++) {
                uint32_t bf[2];
                int nc = wn + nt * 8 + g;
                bf[0] = bs[(kb + tg) * 136 + nc];
                bf[1] = bs[(kb + tg + 4) * 136 + nc];
                mma_tf32(acc[0][nt], af[0], bf);
                mma_tf32(acc[1][nt], af[1], bf);
            }
        }

        if (has) {
            const int nb = cur ^ 1;
            #pragma unroll
            for (int i = 0; i < 2; i++) {
                int l = tid + i * 256;
                int m = l >> 2, kq = (l & 3) * 4;
                uint4 pv;
                pv.x = f2tf32(ar[i*4+0]); pv.y = f2tf32(ar[i*4+1]);
                pv.z = f2tf32(ar[i*4+2]); pv.w = f2tf32(ar[i*4+3]);
                *(uint4*)&As[nb][m * 20 + kq] = pv;
            }
            #pragma unroll
            for (int i = 0; i < 2; i++) {
                int l = tid + i * 256;
                int kk = l >> 5, nq = (l & 31) * 4;
                uint4 pv;
                pv.x = f2tf32(br[i*4+0]); pv.y = f2tf32(br[i*4+1]);
                pv.z = f2tf32(br[i*4+2]); pv.w = f2tf32(br[i*4+3]);
                *(uint4*)&Bs[nb][kk * 136 + nq] = pv;
            }
        }
        __syncthreads();
    }

    // ---- epilogue ----
    #pragma unroll
    for (int mt = 0; mt < 2; mt++) {
        #pragma unroll
        for (int nt = 0; nt < 8; nt++) {
            int r0 = bm + wm + mt * 16 + g;
            int c0 = bn + wn + nt * 8 + tg * 2;
            #pragma unroll
            for (int half = 0; half < 2; half++) {
                int r = r0 + half * 8;
                if (r >= M) continue;
                float mk = (mode == 1 || mode == 2) ? mask[r] : 0.f;
                #pragma unroll
                for (int q = 0; q < 2; q++) {
                    int c = c0 + q;
                    if (c >= N) continue;
                    float v = acc[mt][nt][half * 2 + q];
                    size_t idx = (size_t)r * N + c;
                    float o;
                    if (mode == 0)      o = v;
                    else if (mode == 1) o = res[idx] + v * mk;
                    else if (mode == 2) o = (res[idx] + v) * mk;
                    else if (mode == 3) o = v / (1.f + expf(-v));
                    else                o = res[idx] * v;
                    C[idx] = o;
                }
            }
        }
    }
}

// ---------------- dt / decay ----------------
__global__ void dt_kernel(const float* __restrict__ xn, const float* __restrict__ Wdt,
                          const float* __restrict__ dt_bias, const float* __restrict__ A_log,
                          float* __restrict__ dt, float* __restrict__ a) {
    int t = blockIdx.x;
    int warp = threadIdx.x >> 5, lane = threadIdx.x & 31;
    const float* xr = xn + (size_t)t * Dm;
    float s = 0.f;
    for (int i = lane; i < Dm; i += 32) s += xr[i] * Wdt[(size_t)i * Hh + warp];
    #pragma unroll
    for (int o = 16; o; o >>= 1) s += __shfl_down_sync(0xFFFFFFFFu, s, o);
    if (lane == 0) {
        s += dt_bias[warp];
        float sp = (s > 20.f) ? s : log1pf(expf(s));
        dt[(size_t)t * Hh + warp] = sp;
        a[(size_t)t * Hh + warp] = expf(-expf(A_log[warp]) * sp);
    }
}

// ---------------- SSM scan: 128 blocks (b,h,p-half), 128 threads ----------------
__global__ __launch_bounds__(128, 1)
void scan_kernel(const float* __restrict__ Bm, const float* __restrict__ Cm,
                 const float* __restrict__ u,  const float* __restrict__ dt,
                 const float* __restrict__ a,  const float* __restrict__ z,
                 const float* __restrict__ Dskip, float* __restrict__ gy) {
    const int bh = blockIdx.x >> 1, ph = blockIdx.x & 1;
    const int b = bh >> 4, h = bh & 15;
    const int tid = threadIdx.x;
    const int g = tid >> 5, pl = tid & 31;
    const int p = ph * 32 + pl;

    __shared__ __align__(16) float Bsb[3][128], Csb[3][128];
    __shared__ float uds[3][32], us[3][32], zs[3][32], avs[3];
    __shared__ float red[2][128];

    float hst[32];
    #pragma unroll
    for (int i = 0; i < 32; i++) hst[i] = 0.f;
    const float dsk = Dskip[h];

    // prologue: step 0 -> buf 0
    {
        int base = (b * SS) * Hh + h;
        Bsb[0][tid] = Bm[(size_t)base * 128 + tid];
        Csb[0][tid] = Cm[(size_t)base * 128 + tid];
        if (tid < 32) {
            float uv = u[(size_t)base * 64 + p];
            us[0][tid] = uv;
            uds[0][tid] = uv * dt[base];
            zs[0][tid] = z[(size_t)(b * SS) * DIN + h * 64 + p];
        }
        if (tid == 0) avs[0] = a[base];
    }
    __syncthreads();

    for (int s = 0; s < SS; s++) {
        const int ps = s % 3;
        const float av = avs[ps];
        const float udp = uds[ps][pl];
        const float4* B4 = (const float4*)&Bsb[ps][g * 32];
        const float4* C4 = (const float4*)&Csb[ps][g * 32];
        float acc = 0.f;
        #pragma unroll
        for (int i = 0; i < 8; i++) {
            float4 bb = B4[i], cc = C4[i];
            float h0 = av * hst[4*i+0] + bb.x * udp; hst[4*i+0] = h0; acc += cc.x * h0;
            float h1 = av * hst[4*i+1] + bb.y * udp; hst[4*i+1] = h1; acc += cc.y * h1;
            float h2 = av * hst[4*i+2] + bb.z * udp; hst[4*i+2] = h2; acc += cc.z * h2;
            float h3 = av * hst[4*i+3] + bb.w * udp; hst[4*i+3] = h3; acc += cc.w * h3;
        }
        // prefetch step s+1 into buf (s+1)%3
        if (s + 1 < SS) {
            const int pn = (s + 1) % 3;
            int nb = (b * SS + s + 1) * Hh + h;
            Bsb[pn][tid] = Bm[(size_t)nb * 128 + tid];
            Csb[pn][tid] = Cm[(size_t)nb * 128 + tid];
            if (tid < 32) {
                float uv = u[(size_t)nb * 64 + p];
                us[pn][tid] = uv;
                uds[pn][tid] = uv * dt[nb];
                zs[pn][tid] = z[(size_t)(b * SS + s + 1) * DIN + h * 64 + p];
            }
            if (tid == 0) avs[pn] = a[nb];
        }
        red[s & 1][tid] = acc;
        __syncthreads();
        if (tid < 32) {
            const float* rr = red[s & 1];
            float y = rr[pl] + rr[pl + 32] + rr[pl + 64] + rr[pl + 96];
            float uv = us[ps][pl];
            float zv = zs[ps][pl];
            float sz = zv / (1.f + expf(-zv));
            gy[(size_t)(b * SS + s) * DIN + h * 64 + p] = (y + uv * dsk) * sz;
        }
    }
}

// ---------------- launch ----------------
static inline dim3 gemm_grid(int M, int N) { return dim3((N + 127) / 128, (M + 127) / 128); }

extern "C" void kernel_launch(void* const* d_in, const int* in_sizes, int n_in,
                              void* d_out, int out_size) {
    const float* x      = (const float*)d_in[0];
    const float* mask   = (const float*)d_in[1];
    const float* n1w    = (const float*)d_in[2];
    const float* n2w    = (const float*)d_in[3];
    const float* Wz     = (const float*)d_in[4];
    const float* Wx     = (const float*)d_in[5];
    const float* Wb     = (const float*)d_in[6];
    const float* Wc     = (const float*)d_in[7];
    const float* Wdt    = (const float*)d_in[8];
    const float* dtb    = (const float*)d_in[9];
    const float* A_log  = (const float*)d_in[10];
    const float* D_skip = (const float*)d_in[11];
    const float* Wout   = (const float*)d_in[12];
    const float* w1     = (const float*)d_in[13];
    const float* w2     = (const float*)d_in[14];
    const float* w3     = (const float*)d_in[15];
    float* out = (float*)d_out;

    float *xn, *z, *u, *bm, *cm, *dt, *a, *gy, *x1, *xn2, *g1, *g3;
    cudaGetSymbolAddress((void**)&xn,  g_xn);
    cudaGetSymbolAddress((void**)&z,   g_z);
    cudaGetSymbolAddress((void**)&u,   g_u);
    cudaGetSymbolAddress((void**)&bm,  g_Bm);
    cudaGetSymbolAddress((void**)&cm,  g_Cm);
    cudaGetSymbolAddress((void**)&dt,  g_dt);
    cudaGetSymbolAddress((void**)&a,   g_a);
    cudaGetSymbolAddress((void**)&gy,  g_gy);
    cudaGetSymbolAddress((void**)&x1,  g_x1);
    cudaGetSymbolAddress((void**)&xn2, g_xn2);
    cudaGetSymbolAddress((void**)&g1,  g_g1);
    cudaGetSymbolAddress((void**)&g3,  g_g3);

    rmsnorm_kernel<<<TT, 256>>>(x, n1w, mask, xn, 1);

    mma_gemm<<<gemm_grid(TT, DIN),  256>>>(xn, Wz, z,  TT, DIN,  Dm, 0, nullptr, nullptr);
    mma_gemm<<<gemm_grid(TT, DIN),  256>>>(xn, Wx, u,  TT, DIN,  Dm, 0, nullptr, nullptr);
    mma_gemm<<<gemm_grid(TT, HRDS), 256>>>(xn, Wb, bm, TT, HRDS, Dm, 0, nullptr, nullptr);
    mma_gemm<<<gemm_grid(TT, HRDS), 256>>>(xn, Wc, cm, TT, HRDS, Dm, 0, nullptr, nullptr);

    dt_kernel<<<TT, 512>>>(xn, Wdt, dtb, A_log, dt, a);

    scan_kernel<<<BB * Hh * 2, 128>>>(bm, cm, u, dt, a, z, D_skip, gy);

    // Wout + residual (x + y*mask)
    mma_gemm<<<gemm_grid(TT, Dm), 256>>>(gy, Wout, x1, TT, Dm, DIN, 1, x, mask);

    rmsnorm_kernel<<<TT, 256>>>(x1, n2w, mask, xn2, 0);

    mma_gemm<<<gemm_grid(TT, DFF), 256>>>(xn2, w1, g1, TT, DFF, Dm, 3, nullptr, nullptr); // silu(xn2@w1)
    mma_gemm<<<gemm_grid(TT, DFF), 256>>>(xn2, w3, g3, TT, DFF, Dm, 4, g1, nullptr);      // * (xn2@w3)
    mma_gemm<<<gemm_grid(TT, Dm),  256>>>(g3, w2, out, TT, Dm, DFF, 2, x1, mask);         // (x1+.)*mask
}

// round 3
// speedup vs baseline: 3.7435x; 2.0066x over previous
#include <cuda_runtime.h>
#include <math.h>
#include <stdint.h>

// ---------------- problem constants ----------------
#define Dm     512
#define DIN    1024
#define Hh     16
#define HRDS   2048
#define DFF    1368
#define DFFP   1408            // DFF padded to k-tile multiple (16)
#define NPROJ  6144            // Wz|Wx|Wb|Wc merged N
#define N13    2736            // w1|w3 merged N
#define N13P   2816            // padded to 128
#define BB     4
#define SS     512
#define TT     2048

// ---------------- static scratch ----------------
__device__ __align__(16) float g_xn  [TT*Dm];
__device__ __align__(16) float g_proj[TT*NPROJ];   // z | u | B | C
__device__ __align__(16) float g_dt  [TT*Hh];
__device__ __align__(16) float g_a   [TT*Hh];
__device__ __align__(16) float g_gy  [TT*DIN];
__device__ __align__(16) float g_x1  [TT*Dm];
__device__ __align__(16) float g_xn2 [TT*Dm];
__device__ __align__(16) float g_g13 [TT*N13P];
__device__ __align__(16) float g_g2  [TT*DFFP];
__device__ __align__(16) float g_Wp  [Dm*NPROJ];
__device__ __align__(16) float g_W13 [Dm*N13P];
__device__ __align__(16) float g_Wo  [DIN*Dm];
__device__ __align__(16) float g_W2  [DFFP*Dm];

// ---------------- helpers ----------------
__device__ __forceinline__ uint32_t f2tf32(float v) {
    uint32_t u; asm("cvt.rna.tf32.f32 %0, %1;" : "=r"(u) : "f"(v)); return u;
}
__device__ __forceinline__ float rnd_tf32(float v) { return __uint_as_float(f2tf32(v)); }

#define CP16(dst, src) asm volatile("cp.async.cg.shared.global [%0], [%1], 16;\n" :: "r"(dst), "l"(src))
#define CP4(dst, src)  asm volatile("cp.async.ca.shared.global [%0], [%1], 4;\n"  :: "r"(dst), "l"(src))
#define CP_COMMIT()    asm volatile("cp.async.commit_group;\n")
#define CP_WAIT(n)     asm volatile("cp.async.wait_group %0;\n" :: "n"(n))

__device__ __forceinline__ void mma_tf32(float* c, const uint32_t* a, const uint32_t* b) {
    asm volatile("mma.sync.aligned.m16n8k8.row.col.f32.tf32.tf32.f32 "
        "{%0,%1,%2,%3}, {%4,%5,%6,%7}, {%8,%9}, {%0,%1,%2,%3};"
        : "+f"(c[0]), "+f"(c[1]), "+f"(c[2]), "+f"(c[3])
        : "r"(a[0]), "r"(a[1]), "r"(a[2]), "r"(a[3]), "r"(b[0]), "r"(b[1]));
}

__device__ __forceinline__ float2 ffma2(float2 a, float2 b, float2 c) {
    unsigned long long A = *reinterpret_cast<unsigned long long*>(&a);
    unsigned long long B = *reinterpret_cast<unsigned long long*>(&b);
    unsigned long long C = *reinterpret_cast<unsigned long long*>(&c);
    unsigned long long D;
    asm("fma.rn.f32x2 %0, %1, %2, %3;" : "=l"(D) : "l"(A), "l"(B), "l"(C));
    return *reinterpret_cast<float2*>(&D);
}
__device__ __forceinline__ float2 fmul2(float2 a, float2 b) {
    unsigned long long A = *reinterpret_cast<unsigned long long*>(&a);
    unsigned long long B = *reinterpret_cast<unsigned long long*>(&b);
    unsigned long long D;
    asm("mul.rn.f32x2 %0, %1, %2;" : "=l"(D) : "l"(A), "l"(B));
    return *reinterpret_cast<float2*>(&D);
}

// ---------------- weight pack + tf32 round ----------------
#define R1E (Dm*NPROJ)
#define R2E (R1E + Dm*N13P)
#define R3E (R2E + DIN*Dm)
#define R4E (R3E + DFFP*Dm)
__global__ void pack_kernel(const float* __restrict__ Wz, const float* __restrict__ Wx,
                            const float* __restrict__ Wb, const float* __restrict__ Wc,
                            const float* __restrict__ Wout, const float* __restrict__ w1,
                            const float* __restrict__ w3, const float* __restrict__ w2) {
    for (int i = blockIdx.x * blockDim.x + threadIdx.x; i < R4E; i += gridDim.x * blockDim.x) {
        if (i < R1E) {
            int r = i / NPROJ, c = i % NPROJ;
            float v;
            if      (c < 1024) v = Wz[r * 1024 + c];
            else if (c < 2048) v = Wx[r * 1024 + c - 1024];
            else if (c < 4096) v = Wb[r * 2048 + c - 2048];
            else               v = Wc[r * 2048 + c - 4096];
            g_Wp[i] = rnd_tf32(v);
        } else if (i < R2E) {
            int j = i - R1E; int r = j / N13P, c = j % N13P;
            float v = 0.f;
            if      (c < DFF)  v = w1[r * DFF + c];
            else if (c < N13)  v = w3[r * DFF + c - DFF];
            g_W13[j] = rnd_tf32(v);
        } else if (i < R3E) {
            int j = i - R2E;
            g_Wo[j] = rnd_tf32(Wout[j]);
        } else {
            int j = i - R3E; int r = j >> 9, c = j & 511;
            g_W2[j] = (r < DFF) ? rnd_tf32(w2[r * 512 + c]) : 0.f;
        }
    }
}

// ---------------- rmsnorm (tf32-rounded output) ----------------
__global__ void rmsnorm_kernel(const float* __restrict__ x, const float* __restrict__ w,
                               const float* __restrict__ mask, float* __restrict__ out, int useMask) {
    int t = blockIdx.x;
    const float* xr = x + (size_t)t * Dm;
    float s = 0.f;
    for (int i = threadIdx.x; i < Dm; i += blockDim.x) { float v = xr[i]; s += v * v; }
    __shared__ float red[32];
    #pragma unroll
    for (int o = 16; o; o >>= 1) s += __shfl_down_sync(0xFFFFFFFFu, s, o);
    if ((threadIdx.x & 31) == 0) red[threadIdx.x >> 5] = s;
    __syncthreads();
    if (threadIdx.x < 32) {
        float v = (threadIdx.x < (blockDim.x >> 5)) ? red[threadIdx.x] : 0.f;
        #pragma unroll
        for (int o = 16; o; o >>= 1) v += __shfl_down_sync(0xFFFFFFFFu, v, o);
        if (threadIdx.x == 0) red[0] = v;
    }
    __syncthreads();
    float inv = rsqrtf(red[0] / (float)Dm + 1e-6f);
    float m = useMask ? mask[t] : 1.f;
    float* orow = out + (size_t)t * Dm;
    for (int i = threadIdx.x; i < Dm; i += blockDim.x)
        orow[i] = rnd_tf32(xr[i] * inv * w[i] * m);
}

// ---------------- tf32 GEMM, cp.async 3-stage; all dims multiples of tile ----------------
// mode 0: C=acc   mode 1: C=res+acc*mask[row]   mode 2: C=(res+acc)*mask[row]
#define ASZ (128*20)
#define BSZ (16*136)
__global__ __launch_bounds__(256)
void mma_gemm(const float* __restrict__ A, const float* __restrict__ B,
              float* __restrict__ C, int M, int N, int K,
              int mode, const float* __restrict__ res, const float* __restrict__ mask) {
    extern __shared__ uint32_t smem[];
    uint32_t* Asm = smem;
    uint32_t* Bsm = smem + 3 * ASZ;
    const uint32_t as_sh = (uint32_t)__cvta_generic_to_shared(Asm);
    const uint32_t bs_sh = (uint32_t)__cvta_generic_to_shared(Bsm);

    const int bm = blockIdx.y * 128, bn = blockIdx.x * 128;
    const int tid = threadIdx.x;
    const int lane = tid & 31, w = tid >> 5;
    const int wm = (w >> 1) * 32, wn = (w & 1) * 64;
    const int g = lane >> 2, tg = lane & 3;
    const int kIter = K >> 4;

    // per-thread load coords
    const int am0 = tid >> 2,           akq = (tid & 3) * 4;      // + i*64 rows
    const int bk0 = tid >> 5,           bnq = (tid & 31) * 4;     // + i*8 k-rows

    auto issue = [&](int it) {
        const int st = it % 3;
        const int k0 = it << 4;
        #pragma unroll
        for (int i = 0; i < 2; i++) {
            int m = am0 + i * 64;
            CP16(as_sh + (st * ASZ + m * 20 + akq) * 4,
                 A + (size_t)(bm + m) * K + k0 + akq);
        }
        #pragma unroll
        for (int i = 0; i < 2; i++) {
            int kk = bk0 + i * 8;
            CP16(bs_sh + (st * BSZ + kk * 136 + bnq) * 4,
                 B + (size_t)(k0 + kk) * N + bn + bnq);
        }
        CP_COMMIT();
    };

    float acc[2][8][4];
    #pragma unroll
    for (int mt = 0; mt < 2; mt++)
        #pragma unroll
        for (int nt = 0; nt < 8; nt++)
            #pragma unroll
            for (int q = 0; q < 4; q++) acc[mt][nt][q] = 0.f;

    issue(0);
    issue(1);

    for (int it = 0; it < kIter; it++) {
        CP_WAIT(1);
        __syncthreads();
        if (it + 2 < kIter) issue(it + 2);

        const uint32_t* as = Asm + (it % 3) * ASZ;
        const uint32_t* bs = Bsm + (it % 3) * BSZ;
        #pragma unroll
        for (int kh = 0; kh < 2; kh++) {
            const int kb = kh * 8;
            uint32_t af[2][4];
            #pragma unroll
            for (int mt = 0; mt < 2; mt++) {
                int mr = wm + mt * 16 + g;
                af[mt][0] = as[mr * 20 + kb + tg];
                af[mt][1] = as[(mr + 8) * 20 + kb + tg];
                af[mt][2] = as[mr * 20 + kb + tg + 4];
                af[mt][3] = as[(mr + 8) * 20 + kb + tg + 4];
            }
            #pragma unroll
            for (int nt = 0; nt < 8; nt++) {
                uint32_t bf[2];
                int nc = wn + nt * 8 + g;
                bf[0] = bs[(kb + tg) * 136 + nc];
                bf[1] = bs[(kb + tg + 4) * 136 + nc];
                mma_tf32(acc[0][nt], af[0], bf);
                mma_tf32(acc[1][nt], af[1], bf);
            }
        }
    }

    // epilogue
    #pragma unroll
    for (int mt = 0; mt < 2; mt++) {
        #pragma unroll
        for (int nt = 0; nt < 8; nt++) {
            int r0 = bm + wm + mt * 16 + g;
            int c0 = bn + wn + nt * 8 + tg * 2;
            #pragma unroll
            for (int half = 0; half < 2; half++) {
                int r = r0 + half * 8;
                float mk = (mode != 0) ? mask[r] : 0.f;
                #pragma unroll
                for (int q = 0; q < 2; q++) {
                    int c = c0 + q;
                    float v = acc[mt][nt][half * 2 + q];
                    size_t idx = (size_t)r * N + c;
                    float o;
                    if (mode == 0)      o = v;
                    else if (mode == 1) o = res[idx] + v * mk;
                    else                o = (res[idx] + v) * mk;
                    C[idx] = o;
                }
            }
        }
    }
}

// ---------------- dt / decay ----------------
__global__ void dt_kernel(const float* __restrict__ xn, const float* __restrict__ Wdt,
                          const float* __restrict__ dt_bias, const float* __restrict__ A_log,
                          float* __restrict__ dt, float* __restrict__ a) {
    int t = blockIdx.x;
    int warp = threadIdx.x >> 5, lane = threadIdx.x & 31;
    const float* xr = xn + (size_t)t * Dm;
    float s = 0.f;
    for (int i = lane; i < Dm; i += 32) s += xr[i] * Wdt[(size_t)i * Hh + warp];
    #pragma unroll
    for (int o = 16; o; o >>= 1) s += __shfl_down_sync(0xFFFFFFFFu, s, o);
    if (lane == 0) {
        s += dt_bias[warp];
        float sp = (s > 20.f) ? s : log1pf(expf(s));
        dt[(size_t)t * Hh + warp] = sp;
        a[(size_t)t * Hh + warp] = expf(-expf(A_log[warp]) * sp);
    }
}

// ---------------- SSM scan v2: cp.async 4-deep, shfl reduction, f32x2 ----------------
// grid 128 = (b, h, ph). 128 threads: warp w -> p block, lane = g*8+pp.
__global__ __launch_bounds__(128, 1)
void scan_kernel(const float* __restrict__ proj, const float* __restrict__ dtp,
                 const float* __restrict__ ap, const float* __restrict__ Dskip,
                 float* __restrict__ gy) {
    const int bid = blockIdx.x;
    const int b = bid >> 5, h = (bid >> 1) & 15, ph = bid & 1;
    const int tid = threadIdx.x;
    const int w = tid >> 5, lane = tid & 31;
    const int g = lane >> 3, pp = lane & 7;
    const int pl = w * 8 + pp;            // 0..31 within p-half
    const int p  = ph * 32 + pl;          // 0..63

    __shared__ __align__(16) float Bt[4][4][128];
    __shared__ __align__(16) float Ct[4][4][128];
    __shared__ __align__(16) float ut[4][4][32];
    __shared__ __align__(16) float zt[4][4][32];
    __shared__ __align__(16) float sdt[4][4];
    __shared__ __align__(16) float sa [4][4];

    const uint32_t bt_sh = (uint32_t)__cvta_generic_to_shared(&Bt[0][0][0]);
    const uint32_t ct_sh = (uint32_t)__cvta_generic_to_shared(&Ct[0][0][0]);
    const uint32_t ut_sh = (uint32_t)__cvta_generic_to_shared(&ut[0][0][0]);
    const uint32_t zt_sh = (uint32_t)__cvta_generic_to_shared(&zt[0][0][0]);
    const uint32_t dt_sh = (uint32_t)__cvta_generic_to_shared(&sdt[0][0]);
    const uint32_t sa_sh = (uint32_t)__cvta_generic_to_shared(&sa[0][0]);

    const int colu = h * 64 + ph * 32;

    auto issue = [&](int t) {
        const int st = t & 3;
        const int token0 = b * SS + t * 4;
        {   // B and C: all 128 threads, one 16B chunk each
            int step = tid >> 5, c4 = (tid & 31) << 2;
            const float* srcB = proj + (size_t)(token0 + step) * NPROJ + 2048 + h * 128 + c4;
            CP16(bt_sh + ((st * 4 + step) * 128 + c4) * 4, srcB);
            CP16(ct_sh + ((st * 4 + step) * 128 + c4) * 4, srcB + 2048);
        }
        if (tid < 32) {
            int step = tid >> 3, c4 = (tid & 7) << 2;
            CP16(ut_sh + ((st * 4 + step) * 32 + c4) * 4,
                 proj + (size_t)(token0 + step) * NPROJ + 1024 + colu + c4);
        } else if (tid < 64) {
            int i = tid - 32, step = i >> 3, c4 = (i & 7) << 2;
            CP16(zt_sh + ((st * 4 + step) * 32 + c4) * 4,
                 proj + (size_t)(token0 + step) * NPROJ + colu + c4);
        } else if (tid < 68) {
            int step = tid - 64;
            CP4(dt_sh + (st * 4 + step) * 4, dtp + (size_t)(token0 + step) * Hh + h);
        } else if (tid < 72) {
            int step = tid - 68;
            CP4(sa_sh + (st * 4 + step) * 4, ap + (size_t)(token0 + step) * Hh + h);
        }
        CP_COMMIT();
    };

    float2 hs[16];
    #pragma unroll
    for (int i = 0; i < 16; i++) hs[i] = make_float2(0.f, 0.f);
    const float dsk = Dskip[h];

    issue(0); issue(1); issue(2);

    const int NTILE = SS / 4;   // 128
    for (int t = 0; t < NTILE; t++) {
        CP_WAIT(2);
        __syncthreads();
        if (t + 3 < NTILE) issue(t + 3);
        const int st = t & 3;
        const int token0 = b * SS + t * 4;
        #pragma unroll
        for (int j = 0; j < 4; j++) {
            const float aa = sa[st][j];
            const float udv = ut[st][j][pl] * sdt[st][j];
            const float2 a2 = make_float2(aa, aa);
            const float2 ud2 = make_float2(udv, udv);
            const float2* B2 = (const float2*)&Bt[st][j][g * 32];
            const float2* C2 = (const float2*)&Ct[st][j][g * 32];
            float2 acc0 = make_float2(0.f, 0.f), acc1 = make_float2(0.f, 0.f);
            #pragma unroll
            for (int i = 0; i < 16; i++) {
                float2 bb = B2[i], cc = C2[i];
                float2 tm = fmul2(bb, ud2);
                hs[i] = ffma2(a2, hs[i], tm);
                if (i & 1) acc1 = ffma2(cc, hs[i], acc1);
                else       acc0 = ffma2(cc, hs[i], acc0);
            }
            float y = acc0.x + acc0.y + acc1.x + acc1.y;
            y += __shfl_xor_sync(0xFFFFFFFFu, y, 8);
            y += __shfl_xor_sync(0xFFFFFFFFu, y, 16);
            if (lane < 8) {
                float uv = ut[st][j][pl];
                float zv = zt[st][j][pl];
                float sz = zv / (1.f + expf(-zv));
                gy[(size_t)(token0 + j) * DIN + h * 64 + p] =
                    rnd_tf32((y + uv * dsk) * sz);
            }
        }
    }
}

// ---------------- swiglu: g13 -> g2 (padded, tf32-rounded) ----------------
__global__ void swiglu_kernel(const float* __restrict__ g13, float* __restrict__ g2) {
    int i = blockIdx.x * blockDim.x + threadIdx.x;
    if (i >= TT * DFFP) return;
    int r = i / DFFP, c = i % DFFP;
    float o = 0.f;
    if (c < DFF) {
        float v1 = g13[(size_t)r * N13P + c];
        float v3 = g13[(size_t)r * N13P + DFF + c];
        o = rnd_tf32((v1 / (1.f + expf(-v1))) * v3);
    }
    g2[i] = o;
}

// ---------------- launch ----------------
extern "C" void kernel_launch(void* const* d_in, const int* in_sizes, int n_in,
                              void* d_out, int out_size) {
    const float* x      = (const float*)d_in[0];
    const float* mask   = (const float*)d_in[1];
    const float* n1w    = (const float*)d_in[2];
    const float* n2w    = (const float*)d_in[3];
    const float* Wz     = (const float*)d_in[4];
    const float* Wx     = (const float*)d_in[5];
    const float* Wb     = (const float*)d_in[6];
    const float* Wc     = (const float*)d_in[7];
    const float* Wdt    = (const float*)d_in[8];
    const float* dtb    = (const float*)d_in[9];
    const float* A_log  = (const float*)d_in[10];
    const float* D_skip = (const float*)d_in[11];
    const float* Wout   = (const float*)d_in[12];
    const float* w1     = (const float*)d_in[13];
    const float* w2     = (const float*)d_in[14];
    const float* w3     = (const float*)d_in[15];
    float* out = (float*)d_out;

    float *xn, *proj, *dt, *a, *gy, *x1, *xn2, *g13, *g2;
    float *Wp, *W13, *Wo, *W2;
    cudaGetSymbolAddress((void**)&xn,   g_xn);
    cudaGetSymbolAddress((void**)&proj, g_proj);
    cudaGetSymbolAddress((void**)&dt,   g_dt);
    cudaGetSymbolAddress((void**)&a,    g_a);
    cudaGetSymbolAddress((void**)&gy,   g_gy);
    cudaGetSymbolAddress((void**)&x1,   g_x1);
    cudaGetSymbolAddress((void**)&xn2,  g_xn2);
    cudaGetSymbolAddress((void**)&g13,  g_g13);
    cudaGetSymbolAddress((void**)&g2,   g_g2);
    cudaGetSymbolAddress((void**)&Wp,   g_Wp);
    cudaGetSymbolAddress((void**)&W13,  g_W13);
    cudaGetSymbolAddress((void**)&Wo,   g_Wo);
    cudaGetSymbolAddress((void**)&W2,   g_W2);

    const int gemm_smem = 3 * (ASZ + BSZ) * 4;   // 56832 B
    static int configured = 0;
    if (!configured) {
        cudaFuncSetAttribute(mma_gemm, cudaFuncAttributeMaxDynamicSharedMemorySize, gemm_smem);
        configured = 1;
    }

    pack_kernel<<<2048, 256>>>(Wz, Wx, Wb, Wc, Wout, w1, w3, w2);
    rmsnorm_kernel<<<TT, 256>>>(x, n1w, mask, xn, 1);

    mma_gemm<<<dim3(NPROJ/128, TT/128), 256, gemm_smem>>>(xn, Wp, proj, TT, NPROJ, Dm, 0, nullptr, nullptr);
    dt_kernel<<<TT, 512>>>(xn, Wdt, dtb, A_log, dt, a);

    scan_kernel<<<BB * Hh * 2, 128>>>(proj, dt, a, D_skip, gy);

    mma_gemm<<<dim3(Dm/128, TT/128), 256, gemm_smem>>>(gy, Wo, x1, TT, Dm, DIN, 1, x, mask);
    rmsnorm_kernel<<<TT, 256>>>(x1, n2w, mask, xn2, 0);

    mma_gemm<<<dim3(N13P/128, TT/128), 256, gemm_smem>>>(xn2, W13, g13, TT, N13P, Dm, 0, nullptr, nullptr);
    swiglu_kernel<<<(TT * DFFP + 255) / 256, 256>>>(g13, g2);
    mma_gemm<<<dim3(Dm/128, TT/128), 256, gemm_smem>>>(g2, W2, out, TT, Dm, DFFP, 2, x1, mask);
}

// round 4
// speedup vs baseline: 3.9536x; 1.0561x over previous
#include <cuda_runtime.h>
#include <math.h>
#include <stdint.h>

// ---------------- problem constants ----------------
#define Dm     512
#define DIN    1024
#define Hh     16
#define DFF    1368
#define DFFP   1408            // DFF padded to 128
#define NPROJ  6272            // Wz|Wx|Wb|Wc|Wdt(pad) merged N
#define DTC    6144            // dtraw column base
#define BB     4
#define SS     512
#define TT     2048

// ---------------- static scratch ----------------
__device__ __align__(16) float g_xn  [TT*Dm];
__device__ __align__(16) float g_proj[TT*NPROJ];   // z | u | B | C | dtraw
__device__ __align__(16) float g_gy  [TT*DIN];
__device__ __align__(16) float g_x1  [TT*Dm];
__device__ __align__(16) float g_xn2 [TT*Dm];
__device__ __align__(16) float g_g1  [TT*DFFP];
__device__ __align__(16) float g_g2  [TT*DFFP];
__device__ __align__(16) float g_Wp  [Dm*NPROJ];
__device__ __align__(16) float g_W1  [Dm*DFFP];
__device__ __align__(16) float g_W3  [Dm*DFFP];
__device__ __align__(16) float g_Wo  [DIN*Dm];
__device__ __align__(16) float g_W2  [DFFP*Dm];

// ---------------- helpers ----------------
__device__ __forceinline__ uint32_t f2tf32(float v) {
    uint32_t u; asm("cvt.rna.tf32.f32 %0, %1;" : "=r"(u) : "f"(v)); return u;
}
__device__ __forceinline__ float rnd_tf32(float v) { return __uint_as_float(f2tf32(v)); }

#define CP16(dst, src) asm volatile("cp.async.cg.shared.global [%0], [%1], 16;\n" :: "r"(dst), "l"(src))
#define CP4(dst, src)  asm volatile("cp.async.ca.shared.global [%0], [%1], 4;\n"  :: "r"(dst), "l"(src))
#define CP_COMMIT()    asm volatile("cp.async.commit_group;\n")
#define CP_WAIT(n)     asm volatile("cp.async.wait_group %0;\n" :: "n"(n))

__device__ __forceinline__ void mma_tf32(float* c, const uint32_t* a, const uint32_t* b) {
    asm volatile("mma.sync.aligned.m16n8k8.row.col.f32.tf32.tf32.f32 "
        "{%0,%1,%2,%3}, {%4,%5,%6,%7}, {%8,%9}, {%0,%1,%2,%3};"
        : "+f"(c[0]), "+f"(c[1]), "+f"(c[2]), "+f"(c[3])
        : "r"(a[0]), "r"(a[1]), "r"(a[2]), "r"(a[3]), "r"(b[0]), "r"(b[1]));
}

__device__ __forceinline__ float2 ffma2(float2 a, float2 b, float2 c) {
    unsigned long long A = *reinterpret_cast<unsigned long long*>(&a);
    unsigned long long B = *reinterpret_cast<unsigned long long*>(&b);
    unsigned long long C = *reinterpret_cast<unsigned long long*>(&c);
    unsigned long long D;
    asm("fma.rn.f32x2 %0, %1, %2, %3;" : "=l"(D) : "l"(A), "l"(B), "l"(C));
    return *reinterpret_cast<float2*>(&D);
}
__device__ __forceinline__ float2 fmul2(float2 a, float2 b) {
    unsigned long long A = *reinterpret_cast<unsigned long long*>(&a);
    unsigned long long B = *reinterpret_cast<unsigned long long*>(&b);
    unsigned long long D;
    asm("mul.rn.f32x2 %0, %1, %2;" : "=l"(D) : "l"(A), "l"(B));
    return *reinterpret_cast<float2*>(&D);
}

// ---------------- weight pack + tf32 round ----------------
#define R1E (Dm*NPROJ)
#define R2E (R1E + Dm*DFFP)
#define R3E (R2E + Dm*DFFP)
#define R4E (R3E + DIN*Dm)
#define R5E (R4E + DFFP*Dm)
__global__ void pack_kernel(const float* __restrict__ Wz, const float* __restrict__ Wx,
                            const float* __restrict__ Wb, const float* __restrict__ Wc,
                            const float* __restrict__ Wdt,
                            const float* __restrict__ Wout, const float* __restrict__ w1,
                            const float* __restrict__ w3, const float* __restrict__ w2) {
    for (int i = blockIdx.x * blockDim.x + threadIdx.x; i < R5E; i += gridDim.x * blockDim.x) {
        if (i < R1E) {
            int r = i / NPROJ, c = i % NPROJ;
            float v;
            if      (c < 1024) v = Wz[r * 1024 + c];
            else if (c < 2048) v = Wx[r * 1024 + c - 1024];
            else if (c < 4096) v = Wb[r * 2048 + c - 2048];
            else if (c < 6144) v = Wc[r * 2048 + c - 4096];
            else if (c < 6160) v = Wdt[r * 16 + c - 6144];
            else               v = 0.f;
            g_Wp[i] = rnd_tf32(v);
        } else if (i < R2E) {
            int j = i - R1E; int r = j / DFFP, c = j % DFFP;
            g_W1[j] = (c < DFF) ? rnd_tf32(w1[r * DFF + c]) : 0.f;
        } else if (i < R3E) {
            int j = i - R2E; int r = j / DFFP, c = j % DFFP;
            g_W3[j] = (c < DFF) ? rnd_tf32(w3[r * DFF + c]) : 0.f;
        } else if (i < R4E) {
            int j = i - R3E;
            g_Wo[j] = rnd_tf32(Wout[j]);
        } else {
            int j = i - R4E; int r = j >> 9, c = j & 511;
            g_W2[j] = (r < DFF) ? rnd_tf32(w2[r * 512 + c]) : 0.f;
        }
    }
}

// ---------------- rmsnorm (tf32-rounded output) ----------------
__global__ void rmsnorm_kernel(const float* __restrict__ x, const float* __restrict__ w,
                               const float* __restrict__ mask, float* __restrict__ out, int useMask) {
    int t = blockIdx.x;
    const float* xr = x + (size_t)t * Dm;
    float s = 0.f;
    for (int i = threadIdx.x; i < Dm; i += blockDim.x) { float v = xr[i]; s += v * v; }
    __shared__ float red[32];
    #pragma unroll
    for (int o = 16; o; o >>= 1) s += __shfl_down_sync(0xFFFFFFFFu, s, o);
    if ((threadIdx.x & 31) == 0) red[threadIdx.x >> 5] = s;
    __syncthreads();
    if (threadIdx.x < 32) {
        float v = (threadIdx.x < (blockDim.x >> 5)) ? red[threadIdx.x] : 0.f;
        #pragma unroll
        for (int o = 16; o; o >>= 1) v += __shfl_down_sync(0xFFFFFFFFu, v, o);
        if (threadIdx.x == 0) red[0] = v;
    }
    __syncthreads();
    float inv = rsqrtf(red[0] / (float)Dm + 1e-6f);
    float m = useMask ? mask[t] : 1.f;
    float* orow = out + (size_t)t * Dm;
    for (int i = threadIdx.x; i < Dm; i += blockDim.x)
        orow[i] = rnd_tf32(xr[i] * inv * w[i] * m);
}

// ---------------- tf32 GEMM, cp.async 4-stage; dims multiples of tile ----------------
// mode 0: C=acc               mode 1: C=res+acc*mask[row]
// mode 2: C=(res+acc)*mask    mode 3: C=silu(acc)
// mode 4: C=rnd_tf32(res*acc)
#define NSTAGE 4
#define ASZ (128*20)
template<int BN>
__global__ __launch_bounds__(256, 2)
void mma_gemm(const float* __restrict__ A, const float* __restrict__ B,
              float* __restrict__ C, int M, int N, int K,
              int mode, const float* __restrict__ res, const float* __restrict__ mask) {
    constexpr int BSZ = 16 * (BN + 8);
    constexpr int NT  = BN / 16;          // n-frags per warp
    extern __shared__ uint32_t smem[];
    uint32_t* Asm = smem;
    uint32_t* Bsm = smem + NSTAGE * ASZ;
    const uint32_t as_sh = (uint32_t)__cvta_generic_to_shared(Asm);
    const uint32_t bs_sh = (uint32_t)__cvta_generic_to_shared(Bsm);

    const int bm = blockIdx.y * 128, bn = blockIdx.x * BN;
    const int tid = threadIdx.x;
    const int lane = tid & 31, w = tid >> 5;
    const int wm = (w >> 1) * 32, wn = (w & 1) * (BN / 2);
    const int g = lane >> 2, tg = lane & 3;
    const int kIter = K >> 4;

    const int am0 = tid >> 2, akq = (tid & 3) * 4;
    constexpr int BTPR = BN / 4;                 // threads per B k-row
    const int bk0 = tid / BTPR, bnq = (tid % BTPR) * 4;
    constexpr int BITER = (16 * BTPR + 255) / 256;  // 2 for BN=128, 1 for BN=64

    auto issue = [&](int it) {
        const int st = it % NSTAGE;
        const int k0 = it << 4;
        #pragma unroll
        for (int i = 0; i < 2; i++) {
            int m = am0 + i * 64;
            CP16(as_sh + (st * ASZ + m * 20 + akq) * 4,
                 A + (size_t)(bm + m) * K + k0 + akq);
        }
        #pragma unroll
        for (int i = 0; i < BITER; i++) {
            int kk = bk0 + i * (256 / BTPR);
            CP16(bs_sh + (st * BSZ + kk * (BN + 8) + bnq) * 4,
                 B + (size_t)(k0 + kk) * N + bn + bnq);
        }
        CP_COMMIT();
    };

    float acc[2][NT][4];
    #pragma unroll
    for (int mt = 0; mt < 2; mt++)
        #pragma unroll
        for (int nt = 0; nt < NT; nt++)
            #pragma unroll
            for (int q = 0; q < 4; q++) acc[mt][nt][q] = 0.f;

    issue(0); issue(1); issue(2);

    for (int it = 0; it < kIter; it++) {
        CP_WAIT(2);
        __syncthreads();
        if (it + 3 < kIter) issue(it + 3);

        const uint32_t* as = Asm + (it % NSTAGE) * ASZ;
        const uint32_t* bs = Bsm + (it % NSTAGE) * BSZ;
        #pragma unroll
        for (int kh = 0; kh < 2; kh++) {
            const int kb = kh * 8;
            uint32_t af[2][4];
            #pragma unroll
            for (int mt = 0; mt < 2; mt++) {
                int mr = wm + mt * 16 + g;
                af[mt][0] = as[mr * 20 + kb + tg];
                af[mt][1] = as[(mr + 8) * 20 + kb + tg];
                af[mt][2] = as[mr * 20 + kb + tg + 4];
                af[mt][3] = as[(mr + 8) * 20 + kb + tg + 4];
            }
            #pragma unroll
            for (int nt = 0; nt < NT; nt++) {
                uint32_t bf[2];
                int nc = wn + nt * 8 + g;
                bf[0] = bs[(kb + tg) * (BN + 8) + nc];
                bf[1] = bs[(kb + tg + 4) * (BN + 8) + nc];
                mma_tf32(acc[0][nt], af[0], bf);
                mma_tf32(acc[1][nt], af[1], bf);
            }
        }
    }

    // epilogue
    #pragma unroll
    for (int mt = 0; mt < 2; mt++) {
        #pragma unroll
        for (int nt = 0; nt < NT; nt++) {
            int r0 = bm + wm + mt * 16 + g;
            int c0 = bn + wn + nt * 8 + tg * 2;
            #pragma unroll
            for (int half = 0; half < 2; half++) {
                int r = r0 + half * 8;
                float mk = (mode == 1 || mode == 2) ? mask[r] : 0.f;
                #pragma unroll
                for (int q = 0; q < 2; q++) {
                    int c = c0 + q;
                    float v = acc[mt][nt][half * 2 + q];
                    size_t idx = (size_t)r * N + c;
                    float o;
                    if (mode == 0)      o = v;
                    else if (mode == 1) o = res[idx] + v * mk;
                    else if (mode == 2) o = (res[idx] + v) * mk;
                    else if (mode == 3) o = v / (1.f + expf(-v));
                    else                o = rnd_tf32(res[idx] * v);
                    C[idx] = o;
                }
            }
        }
    }
}

// ---------------- SSM scan: cp.async 4-deep, inline dt/decay, shfl reduction ----------------
// grid 128 = (b, h, ph). 128 threads: warp w -> p block, lane = g*8+pp.
__global__ __launch_bounds__(128, 1)
void scan_kernel(const float* __restrict__ proj, const float* __restrict__ dtb,
                 const float* __restrict__ A_log, const float* __restrict__ Dskip,
                 float* __restrict__ gy) {
    const int bid = blockIdx.x;
    const int b = bid >> 5, h = (bid >> 1) & 15, ph = bid & 1;
    const int tid = threadIdx.x;
    const int w = tid >> 5, lane = tid & 31;
    const int g = lane >> 3, pp = lane & 7;
    const int pl = w * 8 + pp;
    const int p  = ph * 32 + pl;

    __shared__ __align__(16) float Bt[4][4][128];
    __shared__ __align__(16) float Ct[4][4][128];
    __shared__ __align__(16) float ut[4][4][32];
    __shared__ __align__(16) float zt[4][4][32];
    __shared__ __align__(16) float sdtr[4][4];

    const uint32_t bt_sh = (uint32_t)__cvta_generic_to_shared(&Bt[0][0][0]);
    const uint32_t ct_sh = (uint32_t)__cvta_generic_to_shared(&Ct[0][0][0]);
    const uint32_t ut_sh = (uint32_t)__cvta_generic_to_shared(&ut[0][0][0]);
    const uint32_t zt_sh = (uint32_t)__cvta_generic_to_shared(&zt[0][0][0]);
    const uint32_t dt_sh = (uint32_t)__cvta_generic_to_shared(&sdtr[0][0]);

    const int colu = h * 64 + ph * 32;

    auto issue = [&](int t) {
        const int st = t & 3;
        const int token0 = b * SS + t * 4;
        {
            int step = tid >> 5, c4 = (tid & 31) << 2;
            const float* srcB = proj + (size_t)(token0 + step) * NPROJ + 2048 + h * 128 + c4;
            CP16(bt_sh + ((st * 4 + step) * 128 + c4) * 4, srcB);
            CP16(ct_sh + ((st * 4 + step) * 128 + c4) * 4, srcB + 2048);
        }
        if (tid < 32) {
            int step = tid >> 3, c4 = (tid & 7) << 2;
            CP16(ut_sh + ((st * 4 + step) * 32 + c4) * 4,
                 proj + (size_t)(token0 + step) * NPROJ + 1024 + colu + c4);
        } else if (tid < 64) {
            int i = tid - 32, step = i >> 3, c4 = (i & 7) << 2;
            CP16(zt_sh + ((st * 4 + step) * 32 + c4) * 4,
                 proj + (size_t)(token0 + step) * NPROJ + colu + c4);
        } else if (tid < 68) {
            int step = tid - 64;
            CP4(dt_sh + (st * 4 + step) * 4,
                proj + (size_t)(token0 + step) * NPROJ + DTC + h);
        }
        CP_COMMIT();
    };

    float2 hs[16];
    #pragma unroll
    for (int i = 0; i < 16; i++) hs[i] = make_float2(0.f, 0.f);
    const float dsk  = Dskip[h];
    const float dtbh = dtb[h];
    const float eA   = expf(A_log[h]);

    issue(0); issue(1); issue(2);

    const int NTILE = SS / 4;
    for (int t = 0; t < NTILE; t++) {
        CP_WAIT(2);
        __syncthreads();
        if (t + 3 < NTILE) issue(t + 3);
        const int st = t & 3;
        const int token0 = b * SS + t * 4;

        // lanes 0..3 compute softplus(dt) and decay for steps j=lane
        float spv = 0.f, av = 0.f;
        if (lane < 4) {
            float s = sdtr[st][lane] + dtbh;
            spv = (s > 20.f) ? s : log1pf(expf(s));
            av  = expf(-eA * spv);
        }

        #pragma unroll
        for (int j = 0; j < 4; j++) {
            const float sdt_j = __shfl_sync(0xFFFFFFFFu, spv, j);
            const float aa    = __shfl_sync(0xFFFFFFFFu, av,  j);
            const float udv = ut[st][j][pl] * sdt_j;
            const float2 a2 = make_float2(aa, aa);
            const float2 ud2 = make_float2(udv, udv);
            const float2* B2 = (const float2*)&Bt[st][j][g * 32];
            const float2* C2 = (const float2*)&Ct[st][j][g * 32];
            float2 acc0 = make_float2(0.f, 0.f), acc1 = make_float2(0.f, 0.f);
            #pragma unroll
            for (int i = 0; i < 16; i++) {
                float2 bb = B2[i], cc = C2[i];
                float2 tm = fmul2(bb, ud2);
                hs[i] = ffma2(a2, hs[i], tm);
                if (i & 1) acc1 = ffma2(cc, hs[i], acc1);
                else       acc0 = ffma2(cc, hs[i], acc0);
            }
            float y = acc0.x + acc0.y + acc1.x + acc1.y;
            y += __shfl_xor_sync(0xFFFFFFFFu, y, 8);
            y += __shfl_xor_sync(0xFFFFFFFFu, y, 16);
            if (lane < 8) {
                float uv = ut[st][j][pl];
                float zv = zt[st][j][pl];
                float sz = zv / (1.f + expf(-zv));
                gy[(size_t)(token0 + j) * DIN + h * 64 + p] =
                    rnd_tf32((y + uv * dsk) * sz);
            }
        }
    }
}

// ---------------- launch ----------------
extern "C" void kernel_launch(void* const* d_in, const int* in_sizes, int n_in,
                              void* d_out, int out_size) {
    const float* x      = (const float*)d_in[0];
    const float* mask   = (const float*)d_in[1];
    const float* n1w    = (const float*)d_in[2];
    const float* n2w    = (const float*)d_in[3];
    const float* Wz     = (const float*)d_in[4];
    const float* Wx     = (const float*)d_in[5];
    const float* Wb     = (const float*)d_in[6];
    const float* Wc     = (const float*)d_in[7];
    const float* Wdt    = (const float*)d_in[8];
    const float* dtb    = (const float*)d_in[9];
    const float* A_log  = (const float*)d_in[10];
    const float* D_skip = (const float*)d_in[11];
    const float* Wout   = (const float*)d_in[12];
    const float* w1     = (const float*)d_in[13];
    const float* w2     = (const float*)d_in[14];
    const float* w3     = (const float*)d_in[15];
    float* out = (float*)d_out;

    float *xn, *proj, *gy, *x1, *xn2, *g1, *g2;
    float *Wp, *W1, *W3, *Wo, *W2;
    cudaGetSymbolAddress((void**)&xn,   g_xn);
    cudaGetSymbolAddress((void**)&proj, g_proj);
    cudaGetSymbolAddress((void**)&gy,   g_gy);
    cudaGetSymbolAddress((void**)&x1,   g_x1);
    cudaGetSymbolAddress((void**)&xn2,  g_xn2);
    cudaGetSymbolAddress((void**)&g1,   g_g1);
    cudaGetSymbolAddress((void**)&g2,   g_g2);
    cudaGetSymbolAddress((void**)&Wp,   g_Wp);
    cudaGetSymbolAddress((void**)&W1,   g_W1);
    cudaGetSymbolAddress((void**)&W3,   g_W3);
    cudaGetSymbolAddress((void**)&Wo,   g_Wo);
    cudaGetSymbolAddress((void**)&W2,   g_W2);

    const int smem128 = NSTAGE * (ASZ + 16 * 136) * 4;
    const int smem64  = NSTAGE * (ASZ + 16 * 72) * 4;
    static int configured = 0;
    if (!configured) {
        cudaFuncSetAttribute(mma_gemm<128>, cudaFuncAttributeMaxDynamicSharedMemorySize, smem128);
        cudaFuncSetAttribute(mma_gemm<64>,  cudaFuncAttributeMaxDynamicSharedMemorySize, smem64);
        configured = 1;
    }

    pack_kernel<<<2048, 256>>>(Wz, Wx, Wb, Wc, Wdt, Wout, w1, w3, w2);
    rmsnorm_kernel<<<TT, 256>>>(x, n1w, mask, xn, 1);

    // z|u|B|C|dtraw projection
    mma_gemm<128><<<dim3(NPROJ/128, TT/128), 256, smem128>>>(xn, Wp, proj, TT, NPROJ, Dm, 0, nullptr, nullptr);

    scan_kernel<<<BB * Hh * 2, 128>>>(proj, dtb, A_log, D_skip, gy);

    // Wout + residual (x + y*mask)  — skinny N: 64-wide tiles
    mma_gemm<64><<<dim3(Dm/64, TT/128), 256, smem64>>>(gy, Wo, x1, TT, Dm, DIN, 1, x, mask);

    rmsnorm_kernel<<<TT, 256>>>(x1, n2w, mask, xn2, 0);

    mma_gemm<128><<<dim3(DFFP/128, TT/128), 256, smem128>>>(xn2, W1, g1, TT, DFFP, Dm, 3, nullptr, nullptr);
    mma_gemm<128><<<dim3(DFFP/128, TT/128), 256, smem128>>>(xn2, W3, g2, TT, DFFP, Dm, 4, g1, nullptr);
    mma_gemm<64><<<dim3(Dm/64, TT/128), 256, smem64>>>(g2, W2, out, TT, Dm, DFFP, 2, x1, mask);
}

// round 5
// speedup vs baseline: 4.4892x; 1.1355x over previous
#include <cuda_runtime.h>
#include <math.h>
#include <stdint.h>

// ---------------- problem constants ----------------
#define Dm     512
#define DIN    1024
#define Hh     16
#define DFF    1368
#define DFFP   1408
#define NPROJ  6272            // Wz|Wx|Wb|Wc|Wdt(pad)
#define DTC    6144
#define BB     4
#define SS     512
#define TT     2048
#define NCHK   512             // BB*Hh*8 chunks
#define L64    64

// ---------------- static scratch ----------------
__device__ __align__(16) float g_xn  [TT*Dm];
__device__ __align__(16) float g_proj[TT*NPROJ];
__device__ __align__(16) float g_gy  [TT*DIN];
__device__ __align__(16) float g_x1  [TT*Dm];
__device__ __align__(16) float g_xn2 [TT*Dm];
__device__ __align__(16) float g_g1  [TT*DFFP];
__device__ __align__(16) float g_g2  [TT*DFFP];
__device__ __align__(16) float g_Wp  [Dm*NPROJ];
__device__ __align__(16) float g_W1  [Dm*DFFP];
__device__ __align__(16) float g_W3  [Dm*DFFP];
__device__ __align__(16) float g_Wo  [DIN*Dm];
__device__ __align__(16) float g_W2  [DFFP*Dm];
__device__ __align__(16) float g_S   [NCHK*8192];   // chunk state contributions
__device__ __align__(16) float g_h0  [NCHK*8192];   // chunk initial states
__device__ __align__(16) float g_cd  [TT*Hh];       // chunk-local cumsum(dt)

// ---------------- helpers ----------------
__device__ __forceinline__ uint32_t f2tf32(float v) {
    uint32_t u; asm("cvt.rna.tf32.f32 %0, %1;" : "=r"(u) : "f"(v)); return u;
}
__device__ __forceinline__ float rnd_tf32(float v) { return __uint_as_float(f2tf32(v)); }

#define CP16(dst, src) asm volatile("cp.async.cg.shared.global [%0], [%1], 16;\n" :: "r"(dst), "l"(src))
#define CP_COMMIT()    asm volatile("cp.async.commit_group;\n")
#define CP_WAIT(n)     asm volatile("cp.async.wait_group %0;\n" :: "n"(n))

__device__ __forceinline__ void mma_tf32(float* c, const uint32_t* a, const uint32_t* b) {
    asm volatile("mma.sync.aligned.m16n8k8.row.col.f32.tf32.tf32.f32 "
        "{%0,%1,%2,%3}, {%4,%5,%6,%7}, {%8,%9}, {%0,%1,%2,%3};"
        : "+f"(c[0]), "+f"(c[1]), "+f"(c[2]), "+f"(c[3])
        : "r"(a[0]), "r"(a[1]), "r"(a[2]), "r"(a[3]), "r"(b[0]), "r"(b[1]));
}
__device__ __forceinline__ float2 ffma2(float2 a, float2 b, float2 c) {
    unsigned long long A = *reinterpret_cast<unsigned long long*>(&a);
    unsigned long long B = *reinterpret_cast<unsigned long long*>(&b);
    unsigned long long C = *reinterpret_cast<unsigned long long*>(&c);
    unsigned long long D;
    asm("fma.rn.f32x2 %0, %1, %2, %3;" : "=l"(D) : "l"(A), "l"(B), "l"(C));
    return *reinterpret_cast<float2*>(&D);
}
#define F2(a,b) make_float2((a),(b))

// ---------------- weight pack + tf32 round ----------------
#define R1E (Dm*NPROJ)
#define R2E (R1E + Dm*DFFP)
#define R3E (R2E + Dm*DFFP)
#define R4E (R3E + DIN*Dm)
#define R5E (R4E + DFFP*Dm)
__global__ void pack_kernel(const float* __restrict__ Wz, const float* __restrict__ Wx,
                            const float* __restrict__ Wb, const float* __restrict__ Wc,
                            const float* __restrict__ Wdt,
                            const float* __restrict__ Wout, const float* __restrict__ w1,
                            const float* __restrict__ w3, const float* __restrict__ w2) {
    for (int i = blockIdx.x * blockDim.x + threadIdx.x; i < R5E; i += gridDim.x * blockDim.x) {
        if (i < R1E) {
            int r = i / NPROJ, c = i % NPROJ;
            float v;
            if      (c < 1024) v = Wz[r * 1024 + c];
            else if (c < 2048) v = Wx[r * 1024 + c - 1024];
            else if (c < 4096) v = Wb[r * 2048 + c - 2048];
            else if (c < 6144) v = Wc[r * 2048 + c - 4096];
            else if (c < 6160) v = Wdt[r * 16 + c - 6144];
            else               v = 0.f;
            g_Wp[i] = rnd_tf32(v);
        } else if (i < R2E) {
            int j = i - R1E; int r = j / DFFP, c = j % DFFP;
            g_W1[j] = (c < DFF) ? rnd_tf32(w1[r * DFF + c]) : 0.f;
        } else if (i < R3E) {
            int j = i - R2E; int r = j / DFFP, c = j % DFFP;
            g_W3[j] = (c < DFF) ? rnd_tf32(w3[r * DFF + c]) : 0.f;
        } else if (i < R4E) {
            int j = i - R3E;
            g_Wo[j] = rnd_tf32(Wout[j]);
        } else {
            int j = i - R4E; int r = j >> 9, c = j & 511;
            g_W2[j] = (r < DFF) ? rnd_tf32(w2[r * 512 + c]) : 0.f;
        }
    }
}

// ---------------- rmsnorm (tf32-rounded output) ----------------
__global__ void rmsnorm_kernel(const float* __restrict__ x, const float* __restrict__ w,
                               const float* __restrict__ mask, float* __restrict__ out, int useMask) {
    int t = blockIdx.x;
    const float* xr = x + (size_t)t * Dm;
    float s = 0.f;
    for (int i = threadIdx.x; i < Dm; i += blockDim.x) { float v = xr[i]; s += v * v; }
    __shared__ float red[32];
    #pragma unroll
    for (int o = 16; o; o >>= 1) s += __shfl_down_sync(0xFFFFFFFFu, s, o);
    if ((threadIdx.x & 31) == 0) red[threadIdx.x >> 5] = s;
    __syncthreads();
    if (threadIdx.x < 32) {
        float v = (threadIdx.x < (blockDim.x >> 5)) ? red[threadIdx.x] : 0.f;
        #pragma unroll
        for (int o = 16; o; o >>= 1) v += __shfl_down_sync(0xFFFFFFFFu, v, o);
        if (threadIdx.x == 0) red[0] = v;
    }
    __syncthreads();
    float inv = rsqrtf(red[0] / (float)Dm + 1e-6f);
    float m = useMask ? mask[t] : 1.f;
    float* orow = out + (size_t)t * Dm;
    for (int i = threadIdx.x; i < Dm; i += blockDim.x)
        orow[i] = rnd_tf32(xr[i] * inv * w[i] * m);
}

// ---------------- tf32 GEMM (unchanged from R4) ----------------
#define NSTAGE 4
#define ASZ (128*20)
template<int BN>
__global__ __launch_bounds__(256, 2)
void mma_gemm(const float* __restrict__ A, const float* __restrict__ B,
              float* __restrict__ C, int M, int N, int K,
              int mode, const float* __restrict__ res, const float* __restrict__ mask) {
    constexpr int BSZ = 16 * (BN + 8);
    constexpr int NT  = BN / 16;
    extern __shared__ uint32_t smem[];
    uint32_t* Asm = smem;
    uint32_t* Bsm = smem + NSTAGE * ASZ;
    const uint32_t as_sh = (uint32_t)__cvta_generic_to_shared(Asm);
    const uint32_t bs_sh = (uint32_t)__cvta_generic_to_shared(Bsm);

    const int bm = blockIdx.y * 128, bn = blockIdx.x * BN;
    const int tid = threadIdx.x;
    const int lane = tid & 31, w = tid >> 5;
    const int wm = (w >> 1) * 32, wn = (w & 1) * (BN / 2);
    const int g = lane >> 2, tg = lane & 3;
    const int kIter = K >> 4;

    const int am0 = tid >> 2, akq = (tid & 3) * 4;
    constexpr int BTPR = BN / 4;
    const int bk0 = tid / BTPR, bnq = (tid % BTPR) * 4;
    constexpr int BITER = (16 * BTPR + 255) / 256;

    auto issue = [&](int it) {
        const int st = it % NSTAGE;
        const int k0 = it << 4;
        #pragma unroll
        for (int i = 0; i < 2; i++) {
            int m = am0 + i * 64;
            CP16(as_sh + (st * ASZ + m * 20 + akq) * 4,
                 A + (size_t)(bm + m) * K + k0 + akq);
        }
        #pragma unroll
        for (int i = 0; i < BITER; i++) {
            int kk = bk0 + i * (256 / BTPR);
            CP16(bs_sh + (st * BSZ + kk * (BN + 8) + bnq) * 4,
                 B + (size_t)(k0 + kk) * N + bn + bnq);
        }
        CP_COMMIT();
    };

    float acc[2][NT][4];
    #pragma unroll
    for (int mt = 0; mt < 2; mt++)
        #pragma unroll
        for (int nt = 0; nt < NT; nt++)
            #pragma unroll
            for (int q = 0; q < 4; q++) acc[mt][nt][q] = 0.f;

    issue(0); issue(1); issue(2);

    for (int it = 0; it < kIter; it++) {
        CP_WAIT(2);
        __syncthreads();
        if (it + 3 < kIter) issue(it + 3);

        const uint32_t* as = Asm + (it % NSTAGE) * ASZ;
        const uint32_t* bs = Bsm + (it % NSTAGE) * BSZ;
        #pragma unroll
        for (int kh = 0; kh < 2; kh++) {
            const int kb = kh * 8;
            uint32_t af[2][4];
            #pragma unroll
            for (int mt = 0; mt < 2; mt++) {
                int mr = wm + mt * 16 + g;
                af[mt][0] = as[mr * 20 + kb + tg];
                af[mt][1] = as[(mr + 8) * 20 + kb + tg];
                af[mt][2] = as[mr * 20 + kb + tg + 4];
                af[mt][3] = as[(mr + 8) * 20 + kb + tg + 4];
            }
            #pragma unroll
            for (int nt = 0; nt < NT; nt++) {
                uint32_t bf[2];
                int nc = wn + nt * 8 + g;
                bf[0] = bs[(kb + tg) * (BN + 8) + nc];
                bf[1] = bs[(kb + tg + 4) * (BN + 8) + nc];
                mma_tf32(acc[0][nt], af[0], bf);
                mma_tf32(acc[1][nt], af[1], bf);
            }
        }
    }

    #pragma unroll
    for (int mt = 0; mt < 2; mt++) {
        #pragma unroll
        for (int nt = 0; nt < NT; nt++) {
            int r0 = bm + wm + mt * 16 + g;
            int c0 = bn + wn + nt * 8 + tg * 2;
            #pragma unroll
            for (int half = 0; half < 2; half++) {
                int r = r0 + half * 8;
                float mk = (mode == 1 || mode == 2) ? mask[r] : 0.f;
                #pragma unroll
                for (int q = 0; q < 2; q++) {
                    int c = c0 + q;
                    float v = acc[mt][nt][half * 2 + q];
                    size_t idx = (size_t)r * N + c;
                    float o;
                    if (mode == 0)      o = v;
                    else if (mode == 1) o = res[idx] + v * mk;
                    else if (mode == 2) o = (res[idx] + v) * mk;
                    else if (mode == 3) o = v / (1.f + expf(-v));
                    else                o = rnd_tf32(res[idx] * v);
                    C[idx] = o;
                }
            }
        }
    }
}

// ================= chunked SSM scan =================
// Pass 1: per-(b,h,chunk): cumsum(dt) -> cd; S = sum_t w_t * B_t (outer) ud_t
__global__ __launch_bounds__(256, 2)
void scan_pass1(const float* __restrict__ proj, const float* __restrict__ dtb,
                const float* __restrict__ A_log,
                float* __restrict__ Sg, float* __restrict__ cdg) {
    const int blk = blockIdx.x;
    const int c = blk & 7, bh = blk >> 3, h = bh & 15, b = bh >> 4;
    const int tid = threadIdx.x;
    const int tok0 = b * SS + c * L64;

    extern __shared__ float sm1[];
    float* cds = sm1;                 // 64
    float* wts = sm1 + 64;            // 64
    float* Bw  = sm1 + 128;           // 64*132
    float* Ud  = Bw + 64 * 132;       // 64*68

    const float eA = expf(A_log[h]);

    if (tid < 64) {
        float raw = proj[(size_t)(tok0 + tid) * NPROJ + DTC + h] + dtb[h];
        cds[tid] = (raw > 20.f) ? raw : log1pf(expf(raw));
    }
    __syncthreads();
    #pragma unroll
    for (int off = 1; off < 64; off <<= 1) {
        float v = (tid < 64 && tid >= off) ? cds[tid - off] : 0.f;
        __syncthreads();
        if (tid < 64) cds[tid] += v;
        __syncthreads();
    }
    if (tid < 64) {
        cdg[(size_t)(tok0 + tid) * Hh + h] = cds[tid];
        wts[tid] = expf(-eA * (cds[63] - cds[tid]));
    }
    __syncthreads();

    for (int i = tid; i < 64 * 32; i += 256) {
        int t = i >> 5, rq = (i & 31) << 2;
        float4 bv = *(const float4*)&proj[(size_t)(tok0 + t) * NPROJ + 2048 + h * 128 + rq];
        float w = wts[t];
        float4 o; o.x = bv.x * w; o.y = bv.y * w; o.z = bv.z * w; o.w = bv.w * w;
        *(float4*)&Bw[t * 132 + rq] = o;
    }
    for (int i = tid; i < 64 * 16; i += 256) {
        int t = i >> 4, pq = (i & 15) << 2;
        float4 uv = *(const float4*)&proj[(size_t)(tok0 + t) * NPROJ + 1024 + h * 64 + pq];
        float dtv = (t == 0) ? cds[0] : (cds[t] - cds[t - 1]);
        float4 o; o.x = uv.x * dtv; o.y = uv.y * dtv; o.z = uv.z * dtv; o.w = uv.w * dtv;
        *(float4*)&Ud[t * 68 + pq] = o;
    }
    __syncthreads();

    const int rn0 = (tid >> 3) * 4, p0 = (tid & 7) * 8;
    float2 acc[4][4];
    #pragma unroll
    for (int r = 0; r < 4; r++)
        #pragma unroll
        for (int j = 0; j < 4; j++) acc[r][j] = F2(0.f, 0.f);

    for (int t = 0; t < 64; t++) {
        float4 bb = *(const float4*)&Bw[t * 132 + rn0];
        float4 u0 = *(const float4*)&Ud[t * 68 + p0];
        float4 u1 = *(const float4*)&Ud[t * 68 + p0 + 4];
        float br[4] = {bb.x, bb.y, bb.z, bb.w};
        float2 ua = F2(u0.x, u0.y), ub = F2(u0.z, u0.w);
        float2 uc = F2(u1.x, u1.y), ue = F2(u1.z, u1.w);
        #pragma unroll
        for (int r = 0; r < 4; r++) {
            float2 b2 = F2(br[r], br[r]);
            acc[r][0] = ffma2(b2, ua, acc[r][0]);
            acc[r][1] = ffma2(b2, ub, acc[r][1]);
            acc[r][2] = ffma2(b2, uc, acc[r][2]);
            acc[r][3] = ffma2(b2, ue, acc[r][3]);
        }
    }
    float* Sb = Sg + (size_t)blk * 8192;
    #pragma unroll
    for (int r = 0; r < 4; r++) {
        float4 o0; o0.x = acc[r][0].x; o0.y = acc[r][0].y; o0.z = acc[r][1].x; o0.w = acc[r][1].y;
        float4 o1; o1.x = acc[r][2].x; o1.y = acc[r][2].y; o1.z = acc[r][3].x; o1.w = acc[r][3].y;
        *(float4*)&Sb[(rn0 + r) * 64 + p0]     = o0;
        *(float4*)&Sb[(rn0 + r) * 64 + p0 + 4] = o1;
    }
}

// Pass 2: chunk recurrence per (b,h): h0(c) = q63(c-1)*h0(c-1) + S(c-1)
__global__ __launch_bounds__(256, 4)
void scan_pass2(const float* __restrict__ Sg, const float* __restrict__ cdg,
                const float* __restrict__ A_log, float* __restrict__ h0g) {
    const int bh = blockIdx.x, h = bh & 15, b = bh >> 4;
    const int tid = threadIdx.x;
    const float eA = expf(A_log[h]);
    float4 st[8];
    #pragma unroll
    for (int j = 0; j < 8; j++) st[j] = make_float4(0.f, 0.f, 0.f, 0.f);
    for (int c = 0; c < 8; c++) {
        size_t base = ((size_t)(bh * 8 + c)) * 8192;
        #pragma unroll
        for (int j = 0; j < 8; j++)
            *(float4*)&h0g[base + j * 1024 + tid * 4] = st[j];
        float q = expf(-eA * cdg[(size_t)(b * SS + c * L64 + 63) * Hh + h]);
        #pragma unroll
        for (int j = 0; j < 8; j++) {
            float4 s4 = *(const float4*)&Sg[base + j * 1024 + tid * 4];
            st[j].x = q * st[j].x + s4.x;
            st[j].y = q * st[j].y + s4.y;
            st[j].z = q * st[j].z + s4.z;
            st[j].w = q * st[j].w + s4.w;
        }
    }
}

// Pass 3: per-(b,h,chunk): Y = mask(decay∘(C@B^T))@Ud + Q∘(C@h0); gate+skip -> gy
__global__ __launch_bounds__(256, 2)
void scan_pass3(const float* __restrict__ proj, const float* __restrict__ cdg,
                const float* __restrict__ h0g, const float* __restrict__ A_log,
                const float* __restrict__ Dskip, float* __restrict__ gy) {
    const int blk = blockIdx.x;
    const int c = blk & 7, bh = blk >> 3, h = bh & 15, b = bh >> 4;
    const int tid = threadIdx.x;
    const int tok0 = b * SS + c * L64;
    const float eA  = expf(A_log[h]);
    const float dsk = Dskip[h];

    extern __shared__ float sm3[];
    float* Csm  = sm3;                 // 64*132
    float* Bsm  = Csm + 64 * 132;      // 64*132 (later reused for h0 halves as [64][68])
    float* Udsm = Bsm + 64 * 132;      // 64*68
    float* Msm  = Udsm + 64 * 68;      // 64*68
    float* cds  = Msm + 64 * 68;       // 64

    if (tid < 64) cds[tid] = cdg[(size_t)(tok0 + tid) * Hh + h];
    for (int i = tid; i < 64 * 32; i += 256) {
        int t = i >> 5, rq = (i & 31) << 2;
        const float* src = &proj[(size_t)(tok0 + t) * NPROJ + 2048 + h * 128 + rq];
        *(float4*)&Bsm[t * 132 + rq] = *(const float4*)src;
        *(float4*)&Csm[t * 132 + rq] = *(const float4*)(src + 2048);
    }
    __syncthreads();
    for (int i = tid; i < 64 * 16; i += 256) {
        int t = i >> 4, pq = (i & 15) << 2;
        float4 uv = *(const float4*)&proj[(size_t)(tok0 + t) * NPROJ + 1024 + h * 64 + pq];
        float dtv = (t == 0) ? cds[0] : (cds[t] - cds[t - 1]);
        float4 o; o.x = uv.x * dtv; o.y = uv.y * dtv; o.z = uv.z * dtv; o.w = uv.w * dtv;
        *(float4*)&Udsm[t * 68 + pq] = o;
    }
    __syncthreads();

    const int t0 = (tid >> 4) * 4;
    const int q0 = (tid & 15) * 4;     // τ tile in G, p tile in Y

    // ---- G = C @ B^T (packed over k) ----
    float2 ga[4][4];
    #pragma unroll
    for (int i = 0; i < 4; i++)
        #pragma unroll
        for (int j = 0; j < 4; j++) ga[i][j] = F2(0.f, 0.f);
    for (int k = 0; k < 128; k += 4) {
        float4 cr[4], br[4];
        #pragma unroll
        for (int r = 0; r < 4; r++) {
            cr[r] = *(const float4*)&Csm[(t0 + r) * 132 + k];
            br[r] = *(const float4*)&Bsm[(q0 + r) * 132 + k];
        }
        #pragma unroll
        for (int tt = 0; tt < 4; tt++) {
            float2 c2a = F2(cr[tt].x, cr[tt].y), c2b = F2(cr[tt].z, cr[tt].w);
            #pragma unroll
            for (int qq = 0; qq < 4; qq++) {
                ga[tt][qq] = ffma2(c2a, F2(br[qq].x, br[qq].y), ga[tt][qq]);
                ga[tt][qq] = ffma2(c2b, F2(br[qq].z, br[qq].w), ga[tt][qq]);
            }
        }
    }
    #pragma unroll
    for (int tt = 0; tt < 4; tt++) {
        int t = t0 + tt;
        #pragma unroll
        for (int qq = 0; qq < 4; qq++) {
            int q = q0 + qq;
            float g = ga[tt][qq].x + ga[tt][qq].y;
            float w = (q <= t) ? __expf(-eA * (cds[t] - cds[q])) : 0.f;
            Msm[t * 68 + q] = g * w;
        }
    }
    __syncthreads();   // M done; Bsm free

    // prefetch h0 half 0 into regs
    const float* h0b = &h0g[(size_t)blk * 8192];
    float4 hreg[4];
    #pragma unroll
    for (int j = 0; j < 4; j++) {
        int i = tid + j * 256;
        int rn = i >> 4, pq = (i & 15) << 2;
        hreg[j] = *(const float4*)&h0b[rn * 64 + pq];
    }

    // ---- Y_intra = M @ Ud (packed over p) ----
    const int p0 = q0;
    float2 ya[4][2], yb[4][2];
    #pragma unroll
    for (int i = 0; i < 4; i++) {
        ya[i][0] = F2(0.f, 0.f); ya[i][1] = F2(0.f, 0.f);
        yb[i][0] = F2(0.f, 0.f); yb[i][1] = F2(0.f, 0.f);
    }
    for (int q = 0; q < 64; q += 4) {
        float4 mr[4], ur[4];
        #pragma unroll
        for (int r = 0; r < 4; r++) mr[r] = *(const float4*)&Msm[(t0 + r) * 68 + q];
        #pragma unroll
        for (int j = 0; j < 4; j++) ur[j] = *(const float4*)&Udsm[(q + j) * 68 + p0];
        #pragma unroll
        for (int tt = 0; tt < 4; tt++) {
            float4 m4 = mr[tt];
            ya[tt][0] = ffma2(F2(m4.x, m4.x), F2(ur[0].x, ur[0].y), ya[tt][0]);
            ya[tt][1] = ffma2(F2(m4.x, m4.x), F2(ur[0].z, ur[0].w), ya[tt][1]);
            ya[tt][0] = ffma2(F2(m4.y, m4.y), F2(ur[1].x, ur[1].y), ya[tt][0]);
            ya[tt][1] = ffma2(F2(m4.y, m4.y), F2(ur[1].z, ur[1].w), ya[tt][1]);
            ya[tt][0] = ffma2(F2(m4.z, m4.z), F2(ur[2].x, ur[2].y), ya[tt][0]);
            ya[tt][1] = ffma2(F2(m4.z, m4.z), F2(ur[2].z, ur[2].w), ya[tt][1]);
            ya[tt][0] = ffma2(F2(m4.w, m4.w), F2(ur[3].x, ur[3].y), ya[tt][0]);
            ya[tt][1] = ffma2(F2(m4.w, m4.w), F2(ur[3].z, ur[3].w), ya[tt][1]);
        }
    }

    // stage h0 half 0 into Bsm as [64][68]
    float* h0s = Bsm;
    #pragma unroll
    for (int j = 0; j < 4; j++) {
        int i = tid + j * 256;
        int rn = i >> 4, pq = (i & 15) << 2;
        *(float4*)&h0s[rn * 68 + pq] = hreg[j];
    }
    __syncthreads();

    // ---- Y_inter part 1: C[:, 0:64] @ h0[0:64, :] ----
    for (int rn = 0; rn < 64; rn += 4) {
        float4 cr[4], hr[4];
        #pragma unroll
        for (int r = 0; r < 4; r++) cr[r] = *(const float4*)&Csm[(t0 + r) * 132 + rn];
        #pragma unroll
        for (int j = 0; j < 4; j++) hr[j] = *(const float4*)&h0s[(rn + j) * 68 + p0];
        #pragma unroll
        for (int tt = 0; tt < 4; tt++) {
            float4 c4 = cr[tt];
            yb[tt][0] = ffma2(F2(c4.x, c4.x), F2(hr[0].x, hr[0].y), yb[tt][0]);
            yb[tt][1] = ffma2(F2(c4.x, c4.x), F2(hr[0].z, hr[0].w), yb[tt][1]);
            yb[tt][0] = ffma2(F2(c4.y, c4.y), F2(hr[1].x, hr[1].y), yb[tt][0]);
            yb[tt][1] = ffma2(F2(c4.y, c4.y), F2(hr[1].z, hr[1].w), yb[tt][1]);
            yb[tt][0] = ffma2(F2(c4.z, c4.z), F2(hr[2].x, hr[2].y), yb[tt][0]);
            yb[tt][1] = ffma2(F2(c4.z, c4.z), F2(hr[2].z, hr[2].w), yb[tt][1]);
            yb[tt][0] = ffma2(F2(c4.w, c4.w), F2(hr[3].x, hr[3].y), yb[tt][0]);
            yb[tt][1] = ffma2(F2(c4.w, c4.w), F2(hr[3].z, hr[3].w), yb[tt][1]);
        }
    }
    __syncthreads();
    // stage h0 half 1
    #pragma unroll
    for (int j = 0; j < 4; j++) {
        int i = tid + j * 256;
        int rn = i >> 4, pq = (i & 15) << 2;
        *(float4*)&h0s[rn * 68 + pq] = *(const float4*)&h0b[(64 + rn) * 64 + pq];
    }
    __syncthreads();
    // ---- Y_inter part 2: C[:, 64:128] @ h0[64:128, :] ----
    for (int rn = 0; rn < 64; rn += 4) {
        float4 cr[4], hr[4];
        #pragma unroll
        for (int r = 0; r < 4; r++) cr[r] = *(const float4*)&Csm[(t0 + r) * 132 + 64 + rn];
        #pragma unroll
        for (int j = 0; j < 4; j++) hr[j] = *(const float4*)&h0s[(rn + j) * 68 + p0];
        #pragma unroll
        for (int tt = 0; tt < 4; tt++) {
            float4 c4 = cr[tt];
            yb[tt][0] = ffma2(F2(c4.x, c4.x), F2(hr[0].x, hr[0].y), yb[tt][0]);
            yb[tt][1] = ffma2(F2(c4.x, c4.x), F2(hr[0].z, hr[0].w), yb[tt][1]);
            yb[tt][0] = ffma2(F2(c4.y, c4.y), F2(hr[1].x, hr[1].y), yb[tt][0]);
            yb[tt][1] = ffma2(F2(c4.y, c4.y), F2(hr[1].z, hr[1].w), yb[tt][1]);
            yb[tt][0] = ffma2(F2(c4.z, c4.z), F2(hr[2].x, hr[2].y), yb[tt][0]);
            yb[tt][1] = ffma2(F2(c4.z, c4.z), F2(hr[2].z, hr[2].w), yb[tt][1]);
            yb[tt][0] = ffma2(F2(c4.w, c4.w), F2(hr[3].x, hr[3].y), yb[tt][0]);
            yb[tt][1] = ffma2(F2(c4.w, c4.w), F2(hr[3].z, hr[3].w), yb[tt][1]);
        }
    }

    // ---- epilogue: y = Y_intra + Q_t*Y_inter; out = (y + u*Dskip)*silu(z) ----
    #pragma unroll
    for (int tt = 0; tt < 4; tt++) {
        int t = t0 + tt;
        float Qt = __expf(-eA * cds[t]);
        size_t token = (size_t)(tok0 + t);
        float4 uv = *(const float4*)&proj[token * NPROJ + 1024 + h * 64 + p0];
        float4 zv = *(const float4*)&proj[token * NPROJ + h * 64 + p0];
        float y0 = ya[tt][0].x + Qt * yb[tt][0].x;
        float y1 = ya[tt][0].y + Qt * yb[tt][0].y;
        float y2 = ya[tt][1].x + Qt * yb[tt][1].x;
        float y3 = ya[tt][1].y + Qt * yb[tt][1].y;
        float4 o;
        o.x = rnd_tf32((y0 + uv.x * dsk) * (zv.x / (1.f + expf(-zv.x))));
        o.y = rnd_tf32((y1 + uv.y * dsk) * (zv.y / (1.f + expf(-zv.y))));
        o.z = rnd_tf32((y2 + uv.z * dsk) * (zv.z / (1.f + expf(-zv.z))));
        o.w = rnd_tf32((y3 + uv.w * dsk) * (zv.w / (1.f + expf(-zv.w))));
        *(float4*)&gy[token * DIN + h * 64 + p0] = o;
    }
}

// ---------------- launch ----------------
extern "C" void kernel_launch(void* const* d_in, const int* in_sizes, int n_in,
                              void* d_out, int out_size) {
    const float* x      = (const float*)d_in[0];
    const float* mask   = (const float*)d_in[1];
    const float* n1w    = (const float*)d_in[2];
    const float* n2w    = (const float*)d_in[3];
    const float* Wz     = (const float*)d_in[4];
    const float* Wx     = (const float*)d_in[5];
    const float* Wb     = (const float*)d_in[6];
    const float* Wc     = (const float*)d_in[7];
    const float* Wdt    = (const float*)d_in[8];
    const float* dtb    = (const float*)d_in[9];
    const float* A_log  = (const float*)d_in[10];
    const float* D_skip = (const float*)d_in[11];
    const float* Wout   = (const float*)d_in[12];
    const float* w1     = (const float*)d_in[13];
    const float* w2     = (const float*)d_in[14];
    const float* w3     = (const float*)d_in[15];
    float* out = (float*)d_out;

    float *xn, *proj, *gy, *x1, *xn2, *g1, *g2;
    float *Wp, *W1, *W3, *Wo, *W2, *Sg, *h0g, *cdg;
    cudaGetSymbolAddress((void**)&xn,   g_xn);
    cudaGetSymbolAddress((void**)&proj, g_proj);
    cudaGetSymbolAddress((void**)&gy,   g_gy);
    cudaGetSymbolAddress((void**)&x1,   g_x1);
    cudaGetSymbolAddress((void**)&xn2,  g_xn2);
    cudaGetSymbolAddress((void**)&g1,   g_g1);
    cudaGetSymbolAddress((void**)&g2,   g_g2);
    cudaGetSymbolAddress((void**)&Wp,   g_Wp);
    cudaGetSymbolAddress((void**)&W1,   g_W1);
    cudaGetSymbolAddress((void**)&W3,   g_W3);
    cudaGetSymbolAddress((void**)&Wo,   g_Wo);
    cudaGetSymbolAddress((void**)&W2,   g_W2);
    cudaGetSymbolAddress((void**)&Sg,   g_S);
    cudaGetSymbolAddress((void**)&h0g,  g_h0);
    cudaGetSymbolAddress((void**)&cdg,  g_cd);

    const int smem128 = NSTAGE * (ASZ + 16 * 136) * 4;
    const int smem64  = NSTAGE * (ASZ + 16 * 72) * 4;
    const int smemP1  = (128 + 64 * 132 + 64 * 68) * 4;                 // 51712
    const int smemP3  = (64 * 132 * 2 + 64 * 68 * 2 + 64) * 4;          // 102656
    static int configured = 0;
    if (!configured) {
        cudaFuncSetAttribute(mma_gemm<128>, cudaFuncAttributeMaxDynamicSharedMemorySize, smem128);
        cudaFuncSetAttribute(mma_gemm<64>,  cudaFuncAttributeMaxDynamicSharedMemorySize, smem64);
        cudaFuncSetAttribute(scan_pass1, cudaFuncAttributeMaxDynamicSharedMemorySize, smemP1);
        cudaFuncSetAttribute(scan_pass3, cudaFuncAttributeMaxDynamicSharedMemorySize, smemP3);
        configured = 1;
    }

    pack_kernel<<<2048, 256>>>(Wz, Wx, Wb, Wc, Wdt, Wout, w1, w3, w2);
    rmsnorm_kernel<<<TT, 256>>>(x, n1w, mask, xn, 1);

    mma_gemm<128><<<dim3(NPROJ/128, TT/128), 256, smem128>>>(xn, Wp, proj, TT, NPROJ, Dm, 0, nullptr, nullptr);

    scan_pass1<<<NCHK, 256, smemP1>>>(proj, dtb, A_log, Sg, cdg);
    scan_pass2<<<BB * Hh, 256>>>(Sg, cdg, A_log, h0g);
    scan_pass3<<<NCHK, 256, smemP3>>>(proj, cdg, h0g, A_log, D_skip, gy);

    mma_gemm<64><<<dim3(Dm/64, TT/128), 256, smem64>>>(gy, Wo, x1, TT, Dm, DIN, 1, x, mask);
    rmsnorm_kernel<<<TT, 256>>>(x1, n2w, mask, xn2, 0);

    mma_gemm<128><<<dim3(DFFP/128, TT/128), 256, smem128>>>(xn2, W1, g1, TT, DFFP, Dm, 3, nullptr, nullptr);
    mma_gemm<128><<<dim3(DFFP/128, TT/128), 256, smem128>>>(xn2, W3, g2, TT, DFFP, Dm, 4, g1, nullptr);
    mma_gemm<64><<<dim3(Dm/64, TT/128), 256, smem64>>>(g2, W2, out, TT, Dm, DFFP, 2, x1, mask);
}

// round 6
// speedup vs baseline: 4.9443x; 1.1014x over previous
#include <cuda_runtime.h>
#include <math.h>
#include <stdint.h>

// ---------------- problem constants ----------------
#define Dm     512
#define DIN    1024
#define Hh     16
#define DFF    1368
#define DFFP   1408
#define NPROJ  6272            // Wz|Wx|Wb|Wc|Wdt(pad)
#define DTC    6144
#define BB     4
#define SS     512
#define TT     2048
#define NCHK   512
#define L64    64

// ---------------- static scratch ----------------
__device__ __align__(16) float g_xn  [TT*Dm];
__device__ __align__(16) float g_proj[TT*NPROJ];
__device__ __align__(16) float g_gy  [TT*DIN];
__device__ __align__(16) float g_x1  [TT*Dm];
__device__ __align__(16) float g_xn2 [TT*Dm];
__device__ __align__(16) float g_g1  [TT*DFFP];
__device__ __align__(16) float g_g2  [TT*DFFP];
__device__ __align__(16) float g_Wp  [Dm*NPROJ];
__device__ __align__(16) float g_W1  [Dm*DFFP];
__device__ __align__(16) float g_W3  [Dm*DFFP];
__device__ __align__(16) float g_Wo  [DIN*Dm];
__device__ __align__(16) float g_W2  [DFFP*Dm];
__device__ __align__(16) float g_S   [NCHK*8192];
__device__ __align__(16) float g_h0  [NCHK*8192];
__device__ __align__(16) float g_cd  [TT*Hh];

// ---------------- helpers ----------------
__device__ __forceinline__ uint32_t f2tf32(float v) {
    uint32_t u; asm("cvt.rna.tf32.f32 %0, %1;" : "=r"(u) : "f"(v)); return u;
}
__device__ __forceinline__ float rnd_tf32(float v) { return __uint_as_float(f2tf32(v)); }

#define CP16(dst, src) asm volatile("cp.async.cg.shared.global [%0], [%1], 16;\n" :: "r"(dst), "l"(src))
#define CP_COMMIT()    asm volatile("cp.async.commit_group;\n")
#define CP_WAIT(n)     asm volatile("cp.async.wait_group %0;\n" :: "n"(n))

__device__ __forceinline__ void mma_tf32(float* c, const uint32_t* a, const uint32_t* b) {
    asm volatile("mma.sync.aligned.m16n8k8.row.col.f32.tf32.tf32.f32 "
        "{%0,%1,%2,%3}, {%4,%5,%6,%7}, {%8,%9}, {%0,%1,%2,%3};"
        : "+f"(c[0]), "+f"(c[1]), "+f"(c[2]), "+f"(c[3])
        : "r"(a[0]), "r"(a[1]), "r"(a[2]), "r"(a[3]), "r"(b[0]), "r"(b[1]));
}
__device__ __forceinline__ float2 ffma2(float2 a, float2 b, float2 c) {
    unsigned long long A = *reinterpret_cast<unsigned long long*>(&a);
    unsigned long long B = *reinterpret_cast<unsigned long long*>(&b);
    unsigned long long C = *reinterpret_cast<unsigned long long*>(&c);
    unsigned long long D;
    asm("fma.rn.f32x2 %0, %1, %2, %3;" : "=l"(D) : "l"(A), "l"(B), "l"(C));
    return *reinterpret_cast<float2*>(&D);
}
#define F2(a,b) make_float2((a),(b))

// ---------------- weight pack + tf32 round ----------------
#define R1E (Dm*NPROJ)
#define R2E (R1E + Dm*DFFP)
#define R3E (R2E + Dm*DFFP)
#define R4E (R3E + DIN*Dm)
#define R5E (R4E + DFFP*Dm)
__global__ void pack_kernel(const float* __restrict__ Wz, const float* __restrict__ Wx,
                            const float* __restrict__ Wb, const float* __restrict__ Wc,
                            const float* __restrict__ Wdt,
                            const float* __restrict__ Wout, const float* __restrict__ w1,
                            const float* __restrict__ w3, const float* __restrict__ w2) {
    for (int i = blockIdx.x * blockDim.x + threadIdx.x; i < R5E; i += gridDim.x * blockDim.x) {
        if (i < R1E) {
            int r = i / NPROJ, c = i % NPROJ;
            float v;
            if      (c < 1024) v = Wz[r * 1024 + c];
            else if (c < 2048) v = Wx[r * 1024 + c - 1024];
            else if (c < 4096) v = Wb[r * 2048 + c - 2048];
            else if (c < 6144) v = Wc[r * 2048 + c - 4096];
            else if (c < 6160) v = Wdt[r * 16 + c - 6144];
            else               v = 0.f;
            g_Wp[i] = rnd_tf32(v);
        } else if (i < R2E) {
            int j = i - R1E; int r = j / DFFP, c = j % DFFP;
            g_W1[j] = (c < DFF) ? rnd_tf32(w1[r * DFF + c]) : 0.f;
        } else if (i < R3E) {
            int j = i - R2E; int r = j / DFFP, c = j % DFFP;
            g_W3[j] = (c < DFF) ? rnd_tf32(w3[r * DFF + c]) : 0.f;
        } else if (i < R4E) {
            int j = i - R3E;
            g_Wo[j] = rnd_tf32(Wout[j]);
        } else {
            int j = i - R4E; int r = j >> 9, c = j & 511;
            g_W2[j] = (r < DFF) ? rnd_tf32(w2[r * 512 + c]) : 0.f;
        }
    }
}

// ---------------- rmsnorm (vectorized, tf32-rounded output) ----------------
__global__ __launch_bounds__(128)
void rmsnorm_kernel(const float* __restrict__ x, const float* __restrict__ w,
                    const float* __restrict__ mask, float* __restrict__ out, int useMask) {
    int t = blockIdx.x;
    const float4* xr = (const float4*)(x + (size_t)t * Dm);
    float4 v = xr[threadIdx.x];
    float s = v.x * v.x + v.y * v.y + v.z * v.z + v.w * v.w;
    __shared__ float red[4];
    #pragma unroll
    for (int o = 16; o; o >>= 1) s += __shfl_down_sync(0xFFFFFFFFu, s, o);
    if ((threadIdx.x & 31) == 0) red[threadIdx.x >> 5] = s;
    __syncthreads();
    float tot = red[0] + red[1] + red[2] + red[3];
    float inv = rsqrtf(tot / (float)Dm + 1e-6f);
    float m = useMask ? mask[t] : 1.f;
    inv *= m;
    float4 wv = ((const float4*)w)[threadIdx.x];
    float4 o;
    o.x = rnd_tf32(v.x * inv * wv.x);
    o.y = rnd_tf32(v.y * inv * wv.y);
    o.z = rnd_tf32(v.z * inv * wv.z);
    o.w = rnd_tf32(v.w * inv * wv.w);
    ((float4*)(out + (size_t)t * Dm))[threadIdx.x] = o;
}

// ---------------- tf32 GEMM, cp.async 3-stage, K-slab 32 ----------------
// mode 0: C=acc               mode 1: C=res+acc*mask[row]
// mode 2: C=(res+acc)*mask    mode 3: C=silu(acc)
// mode 4: C=rnd_tf32(res*acc)
#define NSTAGE 3
#define ASZ (128*36)
template<int BN>
__global__ __launch_bounds__(256, 2)
void mma_gemm(const float* __restrict__ A, const float* __restrict__ B,
              float* __restrict__ C, int M, int N, int K,
              int mode, const float* __restrict__ res, const float* __restrict__ mask) {
    constexpr int BSZ = 32 * (BN + 8);
    constexpr int NT  = BN / 16;
    extern __shared__ uint32_t smem[];
    uint32_t* Asm = smem;
    uint32_t* Bsm = smem + NSTAGE * ASZ;
    const uint32_t as_sh = (uint32_t)__cvta_generic_to_shared(Asm);
    const uint32_t bs_sh = (uint32_t)__cvta_generic_to_shared(Bsm);

    const int bm = blockIdx.y * 128, bn = blockIdx.x * BN;
    const int tid = threadIdx.x;
    const int lane = tid & 31, w = tid >> 5;
    const int wm = (w >> 1) * 32, wn = (w & 1) * (BN / 2);
    const int g = lane >> 2, tg = lane & 3;
    const int kIter = K >> 5;

    // A: 128 rows x 32 k = 1024 16B-chunks -> 4 per thread
    const int am0 = tid >> 3, akq = (tid & 7) * 4;
    // B: 32 k-rows x BN = (BN/4)*32 chunks
    constexpr int BTPR = BN / 4;                 // chunks per k-row
    const int bk0 = tid / BTPR, bnq = (tid % BTPR) * 4;
    constexpr int BITER = (32 * BTPR) / 256;     // 4 for BN=128, 2 for BN=64

    auto issue = [&](int it) {
        const int st = it % NSTAGE;
        const int k0 = it << 5;
        #pragma unroll
        for (int i = 0; i < 4; i++) {
            int m = am0 + i * 32;
            CP16(as_sh + (st * ASZ + m * 36 + akq) * 4,
                 A + (size_t)(bm + m) * K + k0 + akq);
        }
        #pragma unroll
        for (int i = 0; i < BITER; i++) {
            int kk = bk0 + i * (256 / BTPR);
            CP16(bs_sh + (st * BSZ + kk * (BN + 8) + bnq) * 4,
                 B + (size_t)(k0 + kk) * N + bn + bnq);
        }
        CP_COMMIT();
    };

    float acc[2][NT][4];
    #pragma unroll
    for (int mt = 0; mt < 2; mt++)
        #pragma unroll
        for (int nt = 0; nt < NT; nt++)
            #pragma unroll
            for (int q = 0; q < 4; q++) acc[mt][nt][q] = 0.f;

    issue(0); issue(1);

    for (int it = 0; it < kIter; it++) {
        CP_WAIT(1);
        __syncthreads();
        if (it + 2 < kIter) issue(it + 2);

        const uint32_t* as = Asm + (it % NSTAGE) * ASZ;
        const uint32_t* bs = Bsm + (it % NSTAGE) * BSZ;
        #pragma unroll
        for (int kh = 0; kh < 4; kh++) {
            const int kb = kh * 8;
            uint32_t af[2][4];
            #pragma unroll
            for (int mt = 0; mt < 2; mt++) {
                int mr = wm + mt * 16 + g;
                af[mt][0] = as[mr * 36 + kb + tg];
                af[mt][1] = as[(mr + 8) * 36 + kb + tg];
                af[mt][2] = as[mr * 36 + kb + tg + 4];
                af[mt][3] = as[(mr + 8) * 36 + kb + tg + 4];
            }
            #pragma unroll
            for (int nt = 0; nt < NT; nt++) {
                uint32_t bf[2];
                int nc = wn + nt * 8 + g;
                bf[0] = bs[(kb + tg) * (BN + 8) + nc];
                bf[1] = bs[(kb + tg + 4) * (BN + 8) + nc];
                mma_tf32(acc[0][nt], af[0], bf);
                mma_tf32(acc[1][nt], af[1], bf);
            }
        }
        __syncthreads();
    }

    #pragma unroll
    for (int mt = 0; mt < 2; mt++) {
        #pragma unroll
        for (int nt = 0; nt < NT; nt++) {
            int r0 = bm + wm + mt * 16 + g;
            int c0 = bn + wn + nt * 8 + tg * 2;
            #pragma unroll
            for (int half = 0; half < 2; half++) {
                int r = r0 + half * 8;
                float mk = (mode == 1 || mode == 2) ? mask[r] : 0.f;
                #pragma unroll
                for (int q = 0; q < 2; q++) {
                    int c = c0 + q;
                    float v = acc[mt][nt][half * 2 + q];
                    size_t idx = (size_t)r * N + c;
                    float o;
                    if (mode == 0)      o = v;
                    else if (mode == 1) o = res[idx] + v * mk;
                    else if (mode == 2) o = (res[idx] + v) * mk;
                    else if (mode == 3) o = v / (1.f + expf(-v));
                    else                o = rnd_tf32(res[idx] * v);
                    C[idx] = o;
                }
            }
        }
    }
}

// ================= chunked SSM scan =================
// Pass 1: per-(b,h,chunk): cumsum(dt) -> cd; S = sum_t w_t * B_t (outer) ud_t
__global__ __launch_bounds__(256, 2)
void scan_pass1(const float* __restrict__ proj, const float* __restrict__ dtb,
                const float* __restrict__ A_log,
                float* __restrict__ Sg, float* __restrict__ cdg) {
    const int blk = blockIdx.x;
    const int c = blk & 7, bh = blk >> 3, h = bh & 15, b = bh >> 4;
    const int tid = threadIdx.x;
    const int tok0 = b * SS + c * L64;

    extern __shared__ float sm1[];
    float* cds = sm1;
    float* wts = sm1 + 64;
    float* Bw  = sm1 + 128;
    float* Ud  = Bw + 64 * 132;

    const float eA = expf(A_log[h]);

    if (tid < 64) {
        float raw = proj[(size_t)(tok0 + tid) * NPROJ + DTC + h] + dtb[h];
        cds[tid] = (raw > 20.f) ? raw : log1pf(expf(raw));
    }
    __syncthreads();
    #pragma unroll
    for (int off = 1; off < 64; off <<= 1) {
        float v = (tid < 64 && tid >= off) ? cds[tid - off] : 0.f;
        __syncthreads();
        if (tid < 64) cds[tid] += v;
        __syncthreads();
    }
    if (tid < 64) {
        cdg[(size_t)(tok0 + tid) * Hh + h] = cds[tid];
        wts[tid] = expf(-eA * (cds[63] - cds[tid]));
    }
    __syncthreads();

    for (int i = tid; i < 64 * 32; i += 256) {
        int t = i >> 5, rq = (i & 31) << 2;
        float4 bv = *(const float4*)&proj[(size_t)(tok0 + t) * NPROJ + 2048 + h * 128 + rq];
        float w = wts[t];
        float4 o; o.x = bv.x * w; o.y = bv.y * w; o.z = bv.z * w; o.w = bv.w * w;
        *(float4*)&Bw[t * 132 + rq] = o;
    }
    for (int i = tid; i < 64 * 16; i += 256) {
        int t = i >> 4, pq = (i & 15) << 2;
        float4 uv = *(const float4*)&proj[(size_t)(tok0 + t) * NPROJ + 1024 + h * 64 + pq];
        float dtv = (t == 0) ? cds[0] : (cds[t] - cds[t - 1]);
        float4 o; o.x = uv.x * dtv; o.y = uv.y * dtv; o.z = uv.z * dtv; o.w = uv.w * dtv;
        *(float4*)&Ud[t * 68 + pq] = o;
    }
    __syncthreads();

    const int rn0 = (tid >> 3) * 4, p0 = (tid & 7) * 8;
    float2 acc[4][4];
    #pragma unroll
    for (int r = 0; r < 4; r++)
        #pragma unroll
        for (int j = 0; j < 4; j++) acc[r][j] = F2(0.f, 0.f);

    for (int t = 0; t < 64; t++) {
        float4 bb = *(const float4*)&Bw[t * 132 + rn0];
        float4 u0 = *(const float4*)&Ud[t * 68 + p0];
        float4 u1 = *(const float4*)&Ud[t * 68 + p0 + 4];
        float br[4] = {bb.x, bb.y, bb.z, bb.w};
        float2 ua = F2(u0.x, u0.y), ub = F2(u0.z, u0.w);
        float2 uc = F2(u1.x, u1.y), ue = F2(u1.z, u1.w);
        #pragma unroll
        for (int r = 0; r < 4; r++) {
            float2 b2 = F2(br[r], br[r]);
            acc[r][0] = ffma2(b2, ua, acc[r][0]);
            acc[r][1] = ffma2(b2, ub, acc[r][1]);
            acc[r][2] = ffma2(b2, uc, acc[r][2]);
            acc[r][3] = ffma2(b2, ue, acc[r][3]);
        }
    }
    float* Sb = Sg + (size_t)blk * 8192;
    #pragma unroll
    for (int r = 0; r < 4; r++) {
        float4 o0; o0.x = acc[r][0].x; o0.y = acc[r][0].y; o0.z = acc[r][1].x; o0.w = acc[r][1].y;
        float4 o1; o1.x = acc[r][2].x; o1.y = acc[r][2].y; o1.z = acc[r][3].x; o1.w = acc[r][3].y;
        *(float4*)&Sb[(rn0 + r) * 64 + p0]     = o0;
        *(float4*)&Sb[(rn0 + r) * 64 + p0 + 4] = o1;
    }
}

// Pass 2 (parallel): one thread per (bh, element); serial over 8 chunks.
__global__ __launch_bounds__(256)
void scan_pass2(const float* __restrict__ Sg, const float* __restrict__ cdg,
                const float* __restrict__ A_log, float* __restrict__ h0g) {
    const int gidx = blockIdx.x * blockDim.x + threadIdx.x;   // 64*2048 = 131072 threads, 4 elems each
    const int bh = gidx >> 11, e4 = (gidx & 2047) << 2;
    const int h = bh & 15, b = bh >> 4;
    const float eA = expf(A_log[h]);
    float4 st = make_float4(0.f, 0.f, 0.f, 0.f);
    #pragma unroll
    for (int c = 0; c < 8; c++) {
        size_t base = ((size_t)(bh * 8 + c)) * 8192 + e4;
        *(float4*)&h0g[base] = st;
        float q = expf(-eA * cdg[(size_t)(b * SS + c * L64 + 63) * Hh + h]);
        float4 s4 = *(const float4*)&Sg[base];
        st.x = q * st.x + s4.x;
        st.y = q * st.y + s4.y;
        st.z = q * st.z + s4.z;
        st.w = q * st.w + s4.w;
    }
}

// Pass 3: per-(b,h,chunk): Y = mask(decay∘(C@B^T))@Ud + Q∘(C@h0); gate+skip -> gy
__global__ __launch_bounds__(256, 2)
void scan_pass3(const float* __restrict__ proj, const float* __restrict__ cdg,
                const float* __restrict__ h0g, const float* __restrict__ A_log,
                const float* __restrict__ Dskip, float* __restrict__ gy) {
    const int blk = blockIdx.x;
    const int c = blk & 7, bh = blk >> 3, h = bh & 15, b = bh >> 4;
    const int tid = threadIdx.x;
    const int tok0 = b * SS + c * L64;
    const float eA  = expf(A_log[h]);
    const float dsk = Dskip[h];

    extern __shared__ float sm3[];
    float* Csm  = sm3;
    float* Bsm  = Csm + 64 * 132;
    float* Udsm = Bsm + 64 * 132;
    float* Msm  = Udsm + 64 * 68;
    float* cds  = Msm + 64 * 68;

    if (tid < 64) cds[tid] = cdg[(size_t)(tok0 + tid) * Hh + h];
    for (int i = tid; i < 64 * 32; i += 256) {
        int t = i >> 5, rq = (i & 31) << 2;
        const float* src = &proj[(size_t)(tok0 + t) * NPROJ + 2048 + h * 128 + rq];
        *(float4*)&Bsm[t * 132 + rq] = *(const float4*)src;
        *(float4*)&Csm[t * 132 + rq] = *(const float4*)(src + 2048);
    }
    __syncthreads();
    for (int i = tid; i < 64 * 16; i += 256) {
        int t = i >> 4, pq = (i & 15) << 2;
        float4 uv = *(const float4*)&proj[(size_t)(tok0 + t) * NPROJ + 1024 + h * 64 + pq];
        float dtv = (t == 0) ? cds[0] : (cds[t] - cds[t - 1]);
        float4 o; o.x = uv.x * dtv; o.y = uv.y * dtv; o.z = uv.z * dtv; o.w = uv.w * dtv;
        *(float4*)&Udsm[t * 68 + pq] = o;
    }
    __syncthreads();

    const int t0 = (tid >> 4) * 4;
    const int q0 = (tid & 15) * 4;

    // ---- G = C @ B^T ----
    float2 ga[4][4];
    #pragma unroll
    for (int i = 0; i < 4; i++)
        #pragma unroll
        for (int j = 0; j < 4; j++) ga[i][j] = F2(0.f, 0.f);
    for (int k = 0; k < 128; k += 4) {
        float4 cr[4], br[4];
        #pragma unroll
        for (int r = 0; r < 4; r++) {
            cr[r] = *(const float4*)&Csm[(t0 + r) * 132 + k];
            br[r] = *(const float4*)&Bsm[(q0 + r) * 132 + k];
        }
        #pragma unroll
        for (int tt = 0; tt < 4; tt++) {
            float2 c2a = F2(cr[tt].x, cr[tt].y), c2b = F2(cr[tt].z, cr[tt].w);
            #pragma unroll
            for (int qq = 0; qq < 4; qq++) {
                ga[tt][qq] = ffma2(c2a, F2(br[qq].x, br[qq].y), ga[tt][qq]);
                ga[tt][qq] = ffma2(c2b, F2(br[qq].z, br[qq].w), ga[tt][qq]);
            }
        }
    }
    #pragma unroll
    for (int tt = 0; tt < 4; tt++) {
        int t = t0 + tt;
        #pragma unroll
        for (int qq = 0; qq < 4; qq++) {
            int q = q0 + qq;
            float g = ga[tt][qq].x + ga[tt][qq].y;
            float w = (q <= t) ? __expf(-eA * (cds[t] - cds[q])) : 0.f;
            Msm[t * 68 + q] = g * w;
        }
    }
    __syncthreads();

    const float* h0b = &h0g[(size_t)blk * 8192];
    float4 hreg[4];
    #pragma unroll
    for (int j = 0; j < 4; j++) {
        int i = tid + j * 256;
        int rn = i >> 4, pq = (i & 15) << 2;
        hreg[j] = *(const float4*)&h0b[rn * 64 + pq];
    }

    const int p0 = q0;
    float2 ya[4][2], yb[4][2];
    #pragma unroll
    for (int i = 0; i < 4; i++) {
        ya[i][0] = F2(0.f, 0.f); ya[i][1] = F2(0.f, 0.f);
        yb[i][0] = F2(0.f, 0.f); yb[i][1] = F2(0.f, 0.f);
    }
    for (int q = 0; q < 64; q += 4) {
        float4 mr[4], ur[4];
        #pragma unroll
        for (int r = 0; r < 4; r++) mr[r] = *(const float4*)&Msm[(t0 + r) * 68 + q];
        #pragma unroll
        for (int j = 0; j < 4; j++) ur[j] = *(const float4*)&Udsm[(q + j) * 68 + p0];
        #pragma unroll
        for (int tt = 0; tt < 4; tt++) {
            float4 m4 = mr[tt];
            ya[tt][0] = ffma2(F2(m4.x, m4.x), F2(ur[0].x, ur[0].y), ya[tt][0]);
            ya[tt][1] = ffma2(F2(m4.x, m4.x), F2(ur[0].z, ur[0].w), ya[tt][1]);
            ya[tt][0] = ffma2(F2(m4.y, m4.y), F2(ur[1].x, ur[1].y), ya[tt][0]);
            ya[tt][1] = ffma2(F2(m4.y, m4.y), F2(ur[1].z, ur[1].w), ya[tt][1]);
            ya[tt][0] = ffma2(F2(m4.z, m4.z), F2(ur[2].x, ur[2].y), ya[tt][0]);
            ya[tt][1] = ffma2(F2(m4.z, m4.z), F2(ur[2].z, ur[2].w), ya[tt][1]);
            ya[tt][0] = ffma2(F2(m4.w, m4.w), F2(ur[3].x, ur[3].y), ya[tt][0]);
            ya[tt][1] = ffma2(F2(m4.w, m4.w), F2(ur[3].z, ur[3].w), ya[tt][1]);
        }
    }

    float* h0s = Bsm;
    #pragma unroll
    for (int j = 0; j < 4; j++) {
        int i = tid + j * 256;
        int rn = i >> 4, pq = (i & 15) << 2;
        *(float4*)&h0s[rn * 68 + pq] = hreg[j];
    }
    __syncthreads();

    for (int rn = 0; rn < 64; rn += 4) {
        float4 cr[4], hr[4];
        #pragma unroll
        for (int r = 0; r < 4; r++) cr[r] = *(const float4*)&Csm[(t0 + r) * 132 + rn];
        #pragma unroll
        for (int j = 0; j < 4; j++) hr[j] = *(const float4*)&h0s[(rn + j) * 68 + p0];
        #pragma unroll
        for (int tt = 0; tt < 4; tt++) {
            float4 c4 = cr[tt];
            yb[tt][0] = ffma2(F2(c4.x, c4.x), F2(hr[0].x, hr[0].y), yb[tt][0]);
            yb[tt][1] = ffma2(F2(c4.x, c4.x), F2(hr[0].z, hr[0].w), yb[tt][1]);
            yb[tt][0] = ffma2(F2(c4.y, c4.y), F2(hr[1].x, hr[1].y), yb[tt][0]);
            yb[tt][1] = ffma2(F2(c4.y, c4.y), F2(hr[1].z, hr[1].w), yb[tt][1]);
            yb[tt][0] = ffma2(F2(c4.z, c4.z), F2(hr[2].x, hr[2].y), yb[tt][0]);
            yb[tt][1] = ffma2(F2(c4.z, c4.z), F2(hr[2].z, hr[2].w), yb[tt][1]);
            yb[tt][0] = ffma2(F2(c4.w, c4.w), F2(hr[3].x, hr[3].y), yb[tt][0]);
            yb[tt][1] = ffma2(F2(c4.w, c4.w), F2(hr[3].z, hr[3].w), yb[tt][1]);
        }
    }
    __syncthreads();
    #pragma unroll
    for (int j = 0; j < 4; j++) {
        int i = tid + j * 256;
        int rn = i >> 4, pq = (i & 15) << 2;
        *(float4*)&h0s[rn * 68 + pq] = *(const float4*)&h0b[(64 + rn) * 64 + pq];
    }
    __syncthreads();
    for (int rn = 0; rn < 64; rn += 4) {
        float4 cr[4], hr[4];
        #pragma unroll
        for (int r = 0; r < 4; r++) cr[r] = *(const float4*)&Csm[(t0 + r) * 132 + 64 + rn];
        #pragma unroll
        for (int j = 0; j < 4; j++) hr[j] = *(const float4*)&h0s[(rn + j) * 68 + p0];
        #pragma unroll
        for (int tt = 0; tt < 4; tt++) {
            float4 c4 = cr[tt];
            yb[tt][0] = ffma2(F2(c4.x, c4.x), F2(hr[0].x, hr[0].y), yb[tt][0]);
            yb[tt][1] = ffma2(F2(c4.x, c4.x), F2(hr[0].z, hr[0].w), yb[tt][1]);
            yb[tt][0] = ffma2(F2(c4.y, c4.y), F2(hr[1].x, hr[1].y), yb[tt][0]);
            yb[tt][1] = ffma2(F2(c4.y, c4.y), F2(hr[1].z, hr[1].w), yb[tt][1]);
            yb[tt][0] = ffma2(F2(c4.z, c4.z), F2(hr[2].x, hr[2].y), yb[tt][0]);
            yb[tt][1] = ffma2(F2(c4.z, c4.z), F2(hr[2].z, hr[2].w), yb[tt][1]);
            yb[tt][0] = ffma2(F2(c4.w, c4.w), F2(hr[3].x, hr[3].y), yb[tt][0]);
            yb[tt][1] = ffma2(F2(c4.w, c4.w), F2(hr[3].z, hr[3].w), yb[tt][1]);
        }
    }

    #pragma unroll
    for (int tt = 0; tt < 4; tt++) {
        int t = t0 + tt;
        float Qt = __expf(-eA * cds[t]);
        size_t token = (size_t)(tok0 + t);
        float4 uv = *(const float4*)&proj[token * NPROJ + 1024 + h * 64 + p0];
        float4 zv = *(const float4*)&proj[token * NPROJ + h * 64 + p0];
        float y0 = ya[tt][0].x + Qt * yb[tt][0].x;
        float y1 = ya[tt][0].y + Qt * yb[tt][0].y;
        float y2 = ya[tt][1].x + Qt * yb[tt][1].x;
        float y3 = ya[tt][1].y + Qt * yb[tt][1].y;
        float4 o;
        o.x = rnd_tf32((y0 + uv.x * dsk) * (zv.x / (1.f + expf(-zv.x))));
        o.y = rnd_tf32((y1 + uv.y * dsk) * (zv.y / (1.f + expf(-zv.y))));
        o.z = rnd_tf32((y2 + uv.z * dsk) * (zv.z / (1.f + expf(-zv.z))));
        o.w = rnd_tf32((y3 + uv.w * dsk) * (zv.w / (1.f + expf(-zv.w))));
        *(float4*)&gy[token * DIN + h * 64 + p0] = o;
    }
}

// ---------------- launch ----------------
extern "C" void kernel_launch(void* const* d_in, const int* in_sizes, int n_in,
                              void* d_out, int out_size) {
    const float* x      = (const float*)d_in[0];
    const float* mask   = (const float*)d_in[1];
    const float* n1w    = (const float*)d_in[2];
    const float* n2w    = (const float*)d_in[3];
    const float* Wz     = (const float*)d_in[4];
    const float* Wx     = (const float*)d_in[5];
    const float* Wb     = (const float*)d_in[6];
    const float* Wc     = (const float*)d_in[7];
    const float* Wdt    = (const float*)d_in[8];
    const float* dtb    = (const float*)d_in[9];
    const float* A_log  = (const float*)d_in[10];
    const float* D_skip = (const float*)d_in[11];
    const float* Wout   = (const float*)d_in[12];
    const float* w1     = (const float*)d_in[13];
    const float* w2     = (const float*)d_in[14];
    const float* w3     = (const float*)d_in[15];
    float* out = (float*)d_out;

    float *xn, *proj, *gy, *x1, *xn2, *g1, *g2;
    float *Wp, *W1, *W3, *Wo, *W2, *Sg, *h0g, *cdg;
    cudaGetSymbolAddress((void**)&xn,   g_xn);
    cudaGetSymbolAddress((void**)&proj, g_proj);
    cudaGetSymbolAddress((void**)&gy,   g_gy);
    cudaGetSymbolAddress((void**)&x1,   g_x1);
    cudaGetSymbolAddress((void**)&xn2,  g_xn2);
    cudaGetSymbolAddress((void**)&g1,   g_g1);
    cudaGetSymbolAddress((void**)&g2,   g_g2);
    cudaGetSymbolAddress((void**)&Wp,   g_Wp);
    cudaGetSymbolAddress((void**)&W1,   g_W1);
    cudaGetSymbolAddress((void**)&W3,   g_W3);
    cudaGetSymbolAddress((void**)&Wo,   g_Wo);
    cudaGetSymbolAddress((void**)&W2,   g_W2);
    cudaGetSymbolAddress((void**)&Sg,   g_S);
    cudaGetSymbolAddress((void**)&h0g,  g_h0);
    cudaGetSymbolAddress((void**)&cdg,  g_cd);

    const int smem128 = NSTAGE * (ASZ + 32 * 136) * 4;   // 107,520
    const int smem64  = NSTAGE * (ASZ + 32 * 72)  * 4;   // 82,944
    const int smemP1  = (128 + 64 * 132 + 64 * 68) * 4;
    const int smemP3  = (64 * 132 * 2 + 64 * 68 * 2 + 64) * 4;
    static int configured = 0;
    if (!configured) {
        cudaFuncSetAttribute(mma_gemm<128>, cudaFuncAttributeMaxDynamicSharedMemorySize, smem128);
        cudaFuncSetAttribute(mma_gemm<64>,  cudaFuncAttributeMaxDynamicSharedMemorySize, smem64);
        cudaFuncSetAttribute(scan_pass1, cudaFuncAttributeMaxDynamicSharedMemorySize, smemP1);
        cudaFuncSetAttribute(scan_pass3, cudaFuncAttributeMaxDynamicSharedMemorySize, smemP3);
        configured = 1;
    }

    pack_kernel<<<2048, 256>>>(Wz, Wx, Wb, Wc, Wdt, Wout, w1, w3, w2);
    rmsnorm_kernel<<<TT, 128>>>(x, n1w, mask, xn, 1);

    mma_gemm<128><<<dim3(NPROJ/128, TT/128), 256, smem128>>>(xn, Wp, proj, TT, NPROJ, Dm, 0, nullptr, nullptr);

    scan_pass1<<<NCHK, 256, smemP1>>>(proj, dtb, A_log, Sg, cdg);
    scan_pass2<<<512, 256>>>(Sg, cdg, A_log, h0g);
    scan_pass3<<<NCHK, 256, smemP3>>>(proj, cdg, h0g, A_log, D_skip, gy);

    mma_gemm<64><<<dim3(Dm/64, TT/128), 256, smem64>>>(gy, Wo, x1, TT, Dm, DIN, 1, x, mask);
    rmsnorm_kernel<<<TT, 128>>>(x1, n2w, mask, xn2, 0);

    mma_gemm<128><<<dim3(DFFP/128, TT/128), 256, smem128>>>(xn2, W1, g1, TT, DFFP, Dm, 3, nullptr, nullptr);
    mma_gemm<128><<<dim3(DFFP/128, TT/128), 256, smem128>>>(xn2, W3, g2, TT, DFFP, Dm, 4, g1, nullptr);
    mma_gemm<64><<<dim3(Dm/64, TT/128), 256, smem64>>>(g2, W2, out, TT, Dm, DFFP, 2, x1, mask);
}